// round 9
// baseline (speedup 1.0000x reference)
#include <cuda_runtime.h>
#include <cuda_bf16.h>
#include <cstdint>

// Problem dims
#define BB   32
#define LU   128
#define LC   512
#define SS   30
#define DD   768
#define HH   12
#define DK   64
#define DFF  1152

typedef __nv_bfloat16 bf16;
typedef __nv_bfloat162 bf162;

// ---------------- fp32 scratch ----------------------------------------------
__device__ __align__(256) float g_fea_cur[BB*LU*DD];
__device__ __align__(256) float g_fea_ctx[BB*LC*DD];
__device__ __align__(256) float g_fea_slots[SS*BB*DD];
__device__ __align__(256) float g_cur_attn[BB*LU*DD];
__device__ __align__(256) float g_proj1[BB*SS*DD];
__device__ __align__(256) float g_va[SS*BB*DD];
__device__ __align__(256) float g_bkv0[2*DD];
__device__ __align__(256) float g_bkv1[2*DD];

// ---------------- bf16 hi/lo scratch ---------------------------------------
__device__ __align__(256) bf16 g_wn_h[3*DD*DD],  g_wn_l[3*DD*DD];
__device__ __align__(256) bf16 g_wq_h[2*DD*DD],  g_wq_l[2*DD*DD];
__device__ __align__(256) bf16 g_wkv0_h[DD*2*DD], g_wkv0_l[DD*2*DD];
__device__ __align__(256) bf16 g_wkv1_h[DD*2*DD], g_wkv1_l[DD*2*DD];
__device__ __align__(256) bf16 g_wo_h[2*DD*DD],  g_wo_l[2*DD*DD];
__device__ __align__(256) bf16 g_w1_h[2*DD*DFF], g_w1_l[2*DD*DFF];
__device__ __align__(256) bf16 g_w2_h[2*DFF*DD], g_w2_l[2*DFF*DD];
__device__ __align__(256) bf16 g_xcur_h[BB*LU*DD], g_xcur_l[BB*LU*DD];
__device__ __align__(256) bf16 g_xctx_h[BB*LC*DD], g_xctx_l[BB*LC*DD];
__device__ __align__(256) bf16 g_xpre_h[SS*BB*DD], g_xpre_l[SS*BB*DD];
__device__ __align__(256) bf16 g_fc_h[BB*LU*DD],  g_fc_l[BB*LU*DD];
__device__ __align__(256) bf16 g_fx_h[BB*LC*DD],  g_fx_l[BB*LC*DD];
__device__ __align__(256) bf16 g_fs_h[SS*BB*DD],  g_fs_l[SS*BB*DD];
__device__ __align__(256) bf16 g_lnb_h[BB*LU*DD], g_lnb_l[BB*LU*DD];
__device__ __align__(256) bf16 g_ffh_h[BB*LU*DFF], g_ffh_l[BB*LU*DFF];
__device__ __align__(256) bf16 g_a0_h[BB*LU*DD],  g_a0_l[BB*LU*DD];
__device__ __align__(256) bf16 g_a1_h[BB*SS*DD],  g_a1_l[BB*SS*DD];
__device__ __align__(256) bf16 g_co_h[BB*LU*DD],  g_co_l[BB*LU*DD];
__device__ __align__(256) bf16 g_q0h[BB*LU*DD], g_q0l[BB*LU*DD];
__device__ __align__(256) bf16 g_kv0h[BB*LC*2*DD], g_kv0l[BB*LC*2*DD];
__device__ __align__(256) bf16 g_q1h[SS*BB*DD], g_q1l[SS*BB*DD];
__device__ __align__(256) bf16 g_kv1h[BB*LU*2*DD], g_kv1l[BB*LU*2*DD];

// =================== helpers ================================================
__device__ __forceinline__ uint32_t smem_u32(const void* p) {
    uint32_t a;
    asm("{ .reg .u64 t; cvta.to.shared.u64 t, %1; cvt.u32.u64 %0, t; }" : "=r"(a) : "l"(p));
    return a;
}
__device__ __forceinline__ void ldm_x4(uint32_t* r, uint32_t addr) {
    asm volatile("ldmatrix.sync.aligned.m8n8.x4.shared.b16 {%0,%1,%2,%3}, [%4];"
                 : "=r"(r[0]), "=r"(r[1]), "=r"(r[2]), "=r"(r[3]) : "r"(addr));
}
__device__ __forceinline__ void ldm_x4_t(uint32_t* r, uint32_t addr) {
    asm volatile("ldmatrix.sync.aligned.m8n8.x4.trans.shared.b16 {%0,%1,%2,%3}, [%4];"
                 : "=r"(r[0]), "=r"(r[1]), "=r"(r[2]), "=r"(r[3]) : "r"(addr));
}
__device__ __forceinline__ void mma_bf16(float* c, const uint32_t* a, const uint32_t* b) {
    asm volatile("mma.sync.aligned.m16n8k16.row.col.f32.bf16.bf16.f32 "
                 "{%0,%1,%2,%3}, {%4,%5,%6,%7}, {%8,%9}, {%0,%1,%2,%3};"
                 : "+f"(c[0]), "+f"(c[1]), "+f"(c[2]), "+f"(c[3])
                 : "r"(a[0]), "r"(a[1]), "r"(a[2]), "r"(a[3]), "r"(b[0]), "r"(b[1]));
}
__device__ __forceinline__ void mma_bf16_b(float* c, const uint32_t* a, uint32_t b0, uint32_t b1) {
    asm volatile("mma.sync.aligned.m16n8k16.row.col.f32.bf16.bf16.f32 "
                 "{%0,%1,%2,%3}, {%4,%5,%6,%7}, {%8,%9}, {%0,%1,%2,%3};"
                 : "+f"(c[0]), "+f"(c[1]), "+f"(c[2]), "+f"(c[3])
                 : "r"(a[0]), "r"(a[1]), "r"(a[2]), "r"(a[3]), "r"(b0), "r"(b1));
}
__device__ __forceinline__ void split2(float x, float y, bf162& h, bf162& l) {
    h.x = __float2bfloat16_rn(x); h.y = __float2bfloat16_rn(y);
    l.x = __float2bfloat16_rn(x - __bfloat162float(h.x));
    l.y = __float2bfloat16_rn(y - __bfloat162float(h.y));
}

// --------- merged fp32 -> (hi, lo) bf16 converter, with column packing ------
#define NSEG 12
struct ConvArgs {
    const float* x[NSEG];
    bf16* h[NSEG];
    bf16* l[NSEG];
    int n4[NSEG];
    int ldo4[NSEG];
    int coff4[NSEG];
};
__global__ __launch_bounds__(256)
void conv_split_multi(ConvArgs a)
{
    int s = blockIdx.y;
    int n4 = a.n4[s];
    const float* x = a.x[s];
    bf16* h = a.h[s];
    bf16* l = a.l[s];
    int ldo4 = a.ldo4[s], coff4 = a.coff4[s];
    int stride = gridDim.x * 256;
    for (int i = blockIdx.x * 256 + threadIdx.x; i < n4; i += stride) {
        float4 v = ((const float4*)x)[i];
        bf162 h01, l01, h23, l23;
        split2(v.x, v.y, h01, l01);
        split2(v.z, v.w, h23, l23);
        int o4 = (i / 192) * ldo4 + coff4 + (i % 192);
        ((bf162*)h)[2*o4]   = h01; ((bf162*)h)[2*o4+1] = h23;
        ((bf162*)l)[2*o4]   = l01; ((bf162*)l)[2*o4+1] = l23;
    }
}

// ===== split-bf16 HMMA GEMM, 3-stage cp.async pipeline, 1 barrier/chunk =====
#define A_STRIDE 80
#define B_STRIDE 272
#define KC 32
#define B_TILE 8704            // 32 * 272
#define NSTG 3

template<int MT>
__device__ __forceinline__ void stage_load(
    uint32_t stg, const bf16* __restrict__ Ah, const bf16* __restrict__ Al,
    const bf16* __restrict__ Bh, const bf16* __restrict__ Bl,
    int m0, int n0, int kc0, int M, int N, int K, int tid)
{
    constexpr int SA = MT * A_STRIDE;
    #pragma unroll
    for (int i = 0; i < MT / 64; i++) {
        int ca = tid + (i << 8);
        int r = ca >> 2, seg = ca & 3;
        int m = m0 + r;
        uint32_t dst = stg + (uint32_t)(r * A_STRIDE + seg * 16);
        int sz = (m < M) ? 16 : 0;
        size_t so = (size_t)m * K + kc0 + seg * 8;
        asm volatile("cp.async.cg.shared.global [%0], [%1], 16, %2;"
                     :: "r"(dst), "l"(Ah + so), "r"(sz));
        asm volatile("cp.async.cg.shared.global [%0], [%1], 16, %2;"
                     :: "r"(dst + SA), "l"(Al + so), "r"(sz));
    }
    #pragma unroll
    for (int i = 0; i < 2; i++) {
        int cb = tid + (i << 8);
        int r = cb >> 4, seg = cb & 15;
        uint32_t dst = stg + (uint32_t)(2 * SA + r * B_STRIDE + seg * 16);
        size_t so = (size_t)(kc0 + r) * N + n0 + seg * 8;
        asm volatile("cp.async.cg.shared.global [%0], [%1], 16;"
                     :: "r"(dst), "l"(Bh + so));
        asm volatile("cp.async.cg.shared.global [%0], [%1], 16;"
                     :: "r"(dst + B_TILE), "l"(Bl + so));
    }
    asm volatile("cp.async.commit_group;");
}

template<int MT>
__global__ void __launch_bounds__(256)
mma_gemm(const bf16* __restrict__ Ah, const bf16* __restrict__ Al,
         const bf16* __restrict__ Bh, const bf16* __restrict__ Bl,
         float* __restrict__ C, int M, int N, int K,
         const float* __restrict__ bias, const float* __restrict__ res, int relu,
         bf16* __restrict__ Ch, bf16* __restrict__ Cl)
{
    constexpr int SA  = MT * A_STRIDE;
    constexpr int T_BH = 2 * SA;
    constexpr int T_BL = 2 * SA + B_TILE;
    constexpr int TSTG = 2 * SA + 2 * B_TILE;
    constexpr int WM = (MT == 128) ? 4 : 2;
    constexpr int NP = (MT == 128) ? 4 : 2;

    extern __shared__ __align__(128) char smem[];
    const uint32_t sb = smem_u32(smem);
    const int tid = threadIdx.x;
    const int wid = tid >> 5, lane = tid & 31;
    const int m0 = blockIdx.y * MT, n0 = blockIdx.x * 128;
    const int mw = (wid % WM) * 32;
    const int nw = (wid / WM) * (NP * 16);

    float acc[2][NP * 2][4];
    #pragma unroll
    for (int i = 0; i < 2; i++)
        #pragma unroll
        for (int j = 0; j < NP * 2; j++)
            #pragma unroll
            for (int q = 0; q < 4; q++) acc[i][j][q] = 0.f;

    const int lsub = lane >> 3, lr = lane & 7;
    const uint32_t aOff = (uint32_t)((lr + (lsub & 1) * 8) * A_STRIDE + (lsub >> 1) * 16);
    const uint32_t bOff = (uint32_t)((lr + (lsub & 1) * 8) * B_STRIDE + (lsub >> 1) * 16);

    const int nc = K / KC;
    // prologue: stages 0, 1
    stage_load<MT>(sb + 0 * TSTG, Ah, Al, Bh, Bl, m0, n0, 0, M, N, K, tid);
    if (nc > 1)
        stage_load<MT>(sb + 1 * TSTG, Ah, Al, Bh, Bl, m0, n0, KC, M, N, K, tid);

    int stg = 0;
    for (int c = 0; c < nc; c++) {
        // stage c complete (allow stage c+1 in flight)
        if (c + 1 < nc) asm volatile("cp.async.wait_group 1;");
        else            asm volatile("cp.async.wait_group 0;");
        __syncthreads();

        // prefetch stage c+2 into the buffer freed at iteration c-1
        if (c + 2 < nc) {
            int nstg = stg + 2; if (nstg >= NSTG) nstg -= NSTG;
            stage_load<MT>(sb + nstg * TSTG, Ah, Al, Bh, Bl,
                           m0, n0, (c + 2) * KC, M, N, K, tid);
        }

        const uint32_t st = sb + stg * TSTG;
        #pragma unroll
        for (int ks = 0; ks < KC; ks += 16) {
            uint32_t ah[2][4], al[2][4];
            #pragma unroll
            for (int mi = 0; mi < 2; mi++) {
                uint32_t off = aOff + (uint32_t)((mw + mi * 16) * A_STRIDE + ks * 2);
                ldm_x4(ah[mi], st + off);
                ldm_x4(al[mi], st + SA + off);
            }
            #pragma unroll
            for (int np = 0; np < NP; np++) {
                uint32_t off = bOff + (uint32_t)(ks * B_STRIDE + (nw + np * 16) * 2);
                uint32_t bh[4], bl[4];
                ldm_x4_t(bh, st + T_BH + off);
                ldm_x4_t(bl, st + T_BL + off);
                #pragma unroll
                for (int mi = 0; mi < 2; mi++)
                    #pragma unroll
                    for (int g2 = 0; g2 < 2; g2++)
                        mma_bf16(acc[mi][np * 2 + g2], ah[mi], bh + g2 * 2);
                #pragma unroll
                for (int mi = 0; mi < 2; mi++)
                    #pragma unroll
                    for (int g2 = 0; g2 < 2; g2++)
                        mma_bf16(acc[mi][np * 2 + g2], ah[mi], bl + g2 * 2);
                #pragma unroll
                for (int mi = 0; mi < 2; mi++)
                    #pragma unroll
                    for (int g2 = 0; g2 < 2; g2++)
                        mma_bf16(acc[mi][np * 2 + g2], al[mi], bh + g2 * 2);
            }
        }
        if (++stg >= NSTG) stg = 0;
    }

    // ---- epilogue
    const int qrow = lane >> 2, qcol = (lane & 3) * 2;
    #pragma unroll
    for (int mi = 0; mi < 2; mi++) {
        int r0 = m0 + mw + mi * 16 + qrow;
        #pragma unroll
        for (int ni = 0; ni < NP * 2; ni++) {
            int cidx = n0 + nw + ni * 8 + qcol;
            float* a = acc[mi][ni];
            #pragma unroll
            for (int hh = 0; hh < 2; hh++) {
                int r = r0 + hh * 8;
                if (r >= M) continue;
                float x = a[hh * 2 + 0] + bias[cidx];
                float y = a[hh * 2 + 1] + bias[cidx + 1];
                if (relu) { x = fmaxf(x, 0.f); y = fmaxf(y, 0.f); }
                if (res) {
                    const float2 rv = *(const float2*)&res[(size_t)r * N + cidx];
                    x += rv.x; y += rv.y;
                }
                if (C) {
                    float2 o; o.x = x; o.y = y;
                    *(float2*)&C[(size_t)r * N + cidx] = o;
                }
                if (Ch) {
                    bf162 hv, lv;
                    split2(x, y, hv, lv);
                    *(bf162*)&Ch[(size_t)r * N + cidx] = hv;
                    *(bf162*)&Cl[(size_t)r * N + cidx] = lv;
                }
            }
        }
    }
}

#define STG128 (2 * 128 * A_STRIDE + 2 * B_TILE)
#define STG64  (2 * 64  * A_STRIDE + 2 * B_TILE)

// =================== fused flash attention (split-bf16 HMMA) ================
#define FA_STRIDE 144
#define FA_KH 0
#define FA_KL 18432
#define FA_VH 36864
#define FA_VL 55296
#define FA_MASK 73728
#define FA_SMEM (FA_MASK + 512)

__global__ void __launch_bounds__(256)
flash_attn(const bf16* __restrict__ Qh, const bf16* __restrict__ Ql,
           const bf16* __restrict__ Kh, const bf16* __restrict__ Kl,
           const bf16* __restrict__ Vh, const bf16* __restrict__ Vl,
           const int* __restrict__ mask,
           bf16* __restrict__ Oh, bf16* __restrict__ Ol,
           int Lq, int Lk, int qB, int qS, int oB, int kvld, float scale)
{
    extern __shared__ __align__(128) char smem[];
    const uint32_t sb = smem_u32(smem);
    const float* sbias = (const float*)(smem + FA_MASK);
    const int tid = threadIdx.x, wid = tid >> 5, lane = tid & 31;
    const int z = blockIdx.x, b = z / HH, h = z % HH;
    const int qt = lane >> 2, qc = (lane & 3) * 2;
    const int r0 = wid * 16 + qt, r1 = r0 + 8;
    const int colh = h * DK;

    uint32_t qhf[4][4], qlf[4][4];
    #pragma unroll
    for (int ks = 0; ks < 4; ks++) {
        #pragma unroll
        for (int p = 0; p < 4; p++) {
            int rr = (p & 1) ? r1 : r0;
            int kk = ks * 16 + qc + ((p >> 1) ? 8 : 0);
            if (rr < Lq) {
                size_t off = (size_t)(b * qB + rr * qS) * DD + colh + kk;
                qhf[ks][p] = *(const uint32_t*)(Qh + off);
                qlf[ks][p] = *(const uint32_t*)(Ql + off);
            } else { qhf[ks][p] = 0u; qlf[ks][p] = 0u; }
        }
    }

    float m0 = -1e30f, m1 = -1e30f, l0 = 0.f, l1 = 0.f;
    float oacc[8][4];
    #pragma unroll
    for (int j = 0; j < 8; j++)
        #pragma unroll
        for (int q = 0; q < 4; q++) oacc[j][q] = 0.f;

    const uint32_t ldOffK = (uint32_t)(((lane & 7) + ((lane >> 3) & 1) * 8) * FA_STRIDE
                                       + ((lane >> 4) * 8) * 2);

    const int nch = Lk / 128;
    for (int ch = 0; ch < nch; ch++) {
        const int k0g = ch * 128;
        #pragma unroll
        for (int i = 0; i < 4; i++) {
            int idx = tid + (i << 8);
            int r = idx >> 3, seg = idx & 7;
            size_t src = (size_t)(b * Lk + k0g + r) * kvld + colh + seg * 8;
            uint32_t dst = sb + (uint32_t)(r * FA_STRIDE + seg * 16);
            asm volatile("cp.async.cg.shared.global [%0], [%1], 16;" :: "r"(dst + FA_KH), "l"(Kh + src));
            asm volatile("cp.async.cg.shared.global [%0], [%1], 16;" :: "r"(dst + FA_KL), "l"(Kl + src));
            asm volatile("cp.async.cg.shared.global [%0], [%1], 16;" :: "r"(dst + FA_VH), "l"(Vh + src));
            asm volatile("cp.async.cg.shared.global [%0], [%1], 16;" :: "r"(dst + FA_VL), "l"(Vl + src));
        }
        asm volatile("cp.async.commit_group;");
        if (tid < 128)
            ((float*)(smem + FA_MASK))[tid] = mask[b * Lk + k0g + tid] ? 0.f : -1e9f;
        asm volatile("cp.async.wait_group 0;");
        __syncthreads();

        float sacc[16][4];
        #pragma unroll
        for (int j = 0; j < 16; j++)
            #pragma unroll
            for (int q = 0; q < 4; q++) sacc[j][q] = 0.f;

        #pragma unroll
        for (int ks = 0; ks < 4; ks++) {
            #pragma unroll
            for (int nt = 0; nt < 8; nt++) {
                uint32_t off = ldOffK + (uint32_t)(nt * 16 * FA_STRIDE + ks * 32);
                uint32_t kh4[4], kl4[4];
                ldm_x4(kh4, sb + FA_KH + off);
                ldm_x4(kl4, sb + FA_KL + off);
                #pragma unroll
                for (int sub = 0; sub < 2; sub++)
                    mma_bf16_b(sacc[nt * 2 + sub], qhf[ks], kh4[sub], kh4[sub + 2]);
                #pragma unroll
                for (int sub = 0; sub < 2; sub++)
                    mma_bf16_b(sacc[nt * 2 + sub], qhf[ks], kl4[sub], kl4[sub + 2]);
                #pragma unroll
                for (int sub = 0; sub < 2; sub++)
                    mma_bf16_b(sacc[nt * 2 + sub], qlf[ks], kh4[sub], kh4[sub + 2]);
            }
        }

        float cm0 = -1e30f, cm1 = -1e30f;
        #pragma unroll
        for (int j = 0; j < 16; j++) {
            int kb = j * 8 + qc;
            float b0v = sbias[kb], b1v = sbias[kb + 1];
            sacc[j][0] = sacc[j][0] * scale + b0v;
            sacc[j][1] = sacc[j][1] * scale + b1v;
            sacc[j][2] = sacc[j][2] * scale + b0v;
            sacc[j][3] = sacc[j][3] * scale + b1v;
            cm0 = fmaxf(cm0, fmaxf(sacc[j][0], sacc[j][1]));
            cm1 = fmaxf(cm1, fmaxf(sacc[j][2], sacc[j][3]));
        }
        cm0 = fmaxf(cm0, __shfl_xor_sync(0xFFFFFFFFu, cm0, 1));
        cm0 = fmaxf(cm0, __shfl_xor_sync(0xFFFFFFFFu, cm0, 2));
        cm1 = fmaxf(cm1, __shfl_xor_sync(0xFFFFFFFFu, cm1, 1));
        cm1 = fmaxf(cm1, __shfl_xor_sync(0xFFFFFFFFu, cm1, 2));
        float nm0 = fmaxf(m0, cm0), nm1 = fmaxf(m1, cm1);
        float al0 = __expf(m0 - nm0), al1 = __expf(m1 - nm1);
        m0 = nm0; m1 = nm1;

        float ps0 = 0.f, ps1 = 0.f;
        #pragma unroll
        for (int j = 0; j < 16; j++) {
            float p0 = __expf(sacc[j][0] - nm0), p1 = __expf(sacc[j][1] - nm0);
            float p2 = __expf(sacc[j][2] - nm1), p3 = __expf(sacc[j][3] - nm1);
            ps0 += p0 + p1; ps1 += p2 + p3;
            sacc[j][0] = p0; sacc[j][1] = p1; sacc[j][2] = p2; sacc[j][3] = p3;
        }
        ps0 += __shfl_xor_sync(0xFFFFFFFFu, ps0, 1);
        ps0 += __shfl_xor_sync(0xFFFFFFFFu, ps0, 2);
        ps1 += __shfl_xor_sync(0xFFFFFFFFu, ps1, 1);
        ps1 += __shfl_xor_sync(0xFFFFFFFFu, ps1, 2);
        l0 = l0 * al0 + ps0; l1 = l1 * al1 + ps1;
        #pragma unroll
        for (int j = 0; j < 8; j++) {
            oacc[j][0] *= al0; oacc[j][1] *= al0;
            oacc[j][2] *= al1; oacc[j][3] *= al1;
        }

        #pragma unroll
        for (int kk = 0; kk < 8; kk++) {
            uint32_t ahp[4], alp[4];
            #pragma unroll
            for (int jj = 0; jj < 2; jj++) {
                const float* sp = sacc[2 * kk + jj];
                bf162 h01, l01, h23, l23;
                split2(sp[0], sp[1], h01, l01);
                split2(sp[2], sp[3], h23, l23);
                ahp[jj * 2 + 0] = *(uint32_t*)&h01; ahp[jj * 2 + 1] = *(uint32_t*)&h23;
                alp[jj * 2 + 0] = *(uint32_t*)&l01; alp[jj * 2 + 1] = *(uint32_t*)&l23;
            }
            #pragma unroll
            for (int dt = 0; dt < 4; dt++) {
                uint32_t off = ldOffK + (uint32_t)(kk * 16 * FA_STRIDE + dt * 32);
                uint32_t vh4[4], vl4[4];
                ldm_x4_t(vh4, sb + FA_VH + off);
                ldm_x4_t(vl4, sb + FA_VL + off);
                #pragma unroll
                for (int sub = 0; sub < 2; sub++)
                    mma_bf16_b(oacc[dt * 2 + sub], ahp, vh4[sub*2], vh4[sub*2+1]);
                #pragma unroll
                for (int sub = 0; sub < 2; sub++)
                    mma_bf16_b(oacc[dt * 2 + sub], alp, vh4[sub*2], vh4[sub*2+1]);
                #pragma unroll
                for (int sub = 0; sub < 2; sub++)
                    mma_bf16_b(oacc[dt * 2 + sub], ahp, vl4[sub*2], vl4[sub*2+1]);
            }
        }
        __syncthreads();
    }

    float inv0 = 1.f / l0, inv1 = 1.f / l1;
    #pragma unroll
    for (int j = 0; j < 8; j++) {
        int col = colh + j * 8 + qc;
        if (r0 < Lq) {
            bf162 hv, lv;
            split2(oacc[j][0] * inv0, oacc[j][1] * inv0, hv, lv);
            size_t off = (size_t)(b * oB + r0) * DD + col;
            *(bf162*)(Oh + off) = hv; *(bf162*)(Ol + off) = lv;
        }
        if (r1 < Lq) {
            bf162 hv, lv;
            split2(oacc[j][2] * inv1, oacc[j][3] * inv1, hv, lv);
            size_t off = (size_t)(b * oB + r1) * DD + col;
            *(bf162*)(Oh + off) = hv; *(bf162*)(Ol + off) = lv;
        }
    }
}

// ------- LayerNorm: warp per row, single pass, register resident ------------
__global__ __launch_bounds__(256)
void ln_warp(const float* __restrict__ x, float* __restrict__ y,
             bf16* __restrict__ yh, bf16* __restrict__ yl,
             const float* __restrict__ g, const float* __restrict__ be)
{
    const int lane = threadIdx.x & 31;
    const size_t row = (size_t)(blockIdx.x * 8) + (threadIdx.x >> 5);
    const float* xr = x + row * DD;

    float4 v[6];
    float s = 0.f, s2 = 0.f;
    #pragma unroll
    for (int i = 0; i < 6; i++) {
        v[i] = *(const float4*)&xr[i * 128 + lane * 4];
        s  += v[i].x + v[i].y + v[i].z + v[i].w;
        s2 += v[i].x * v[i].x + v[i].y * v[i].y + v[i].z * v[i].z + v[i].w * v[i].w;
    }
    #pragma unroll
    for (int o = 16; o > 0; o >>= 1) {
        s  += __shfl_xor_sync(0xFFFFFFFFu, s, o);
        s2 += __shfl_xor_sync(0xFFFFFFFFu, s2, o);
    }
    const float mean = s * (1.f / DD);
    const float var  = s2 * (1.f / DD) - mean * mean;
    const float rstd = rsqrtf(var + 1e-5f);

    #pragma unroll
    for (int i = 0; i < 6; i++) {
        int col = i * 128 + lane * 4;
        float4 gv = *(const float4*)&g[col];
        float4 bv = *(const float4*)&be[col];
        float4 o;
        o.x = (v[i].x - mean) * rstd * gv.x + bv.x;
        o.y = (v[i].y - mean) * rstd * gv.y + bv.y;
        o.z = (v[i].z - mean) * rstd * gv.z + bv.z;
        o.w = (v[i].w - mean) * rstd * gv.w + bv.w;
        if (y) *(float4*)&y[row * DD + col] = o;
        if (yh) {
            bf162 h01, l01, h23, l23;
            split2(o.x, o.y, h01, l01);
            split2(o.z, o.w, h23, l23);
            *(bf162*)&yh[row * DD + col]     = h01;
            *(bf162*)&yh[row * DD + col + 2] = h23;
            *(bf162*)&yl[row * DD + col]     = l01;
            *(bf162*)&yl[row * DD + col + 2] = l23;
        }
    }
}

// ---------------- va = fea_slots[S,B,D] + proj1[B,S,D] transposed -----------
__global__ __launch_bounds__(256)
void va_kernel(const float* __restrict__ slots, const float* __restrict__ proj,
               float* __restrict__ va)
{
    int idx = blockIdx.x * 256 + threadIdx.x;
    if (idx >= SS * BB * DD) return;
    int d = idx % DD;
    int r = idx / DD;
    int s = r / BB, b = r % BB;
    va[idx] = slots[idx] + proj[((long long)b * SS + s) * DD + d];
}

// ---------------- host-side helpers ----------------------------------------
template<typename T>
static T* sym(const void* s) { void* p = nullptr; cudaGetSymbolAddress(&p, s); return (T*)p; }

static void run_lin_s(cudaStream_t st, const bf16* Ah, const bf16* Al,
                      const bf16* Wh, const bf16* Wl,
                      float* C, int M, int N, int K,
                      const float* bias, const float* res, int relu,
                      bf16* Ch = nullptr, bf16* Cl = nullptr)
{
    int ctas128 = (N / 128) * ((M + 127) / 128);
    if (M <= 4096 && ctas128 < 232) {
        dim3 grid(N / 128, (M + 63) / 64);
        mma_gemm<64><<<grid, 256, NSTG * STG64, st>>>(Ah, Al, Wh, Wl, C, M, N, K, bias, res, relu, Ch, Cl);
    } else {
        dim3 grid(N / 128, (M + 127) / 128);
        mma_gemm<128><<<grid, 256, NSTG * STG128, st>>>(Ah, Al, Wh, Wl, C, M, N, K, bias, res, relu, Ch, Cl);
    }
}

extern "C" void kernel_launch(void* const* d_in, const int* in_sizes, int n_in,
                              void* d_out, int out_size)
{
    static bool s_init = false;
    static cudaStream_t s1, s2;
    static cudaEvent_t e0, e1, e2;
    if (!s_init) {
        cudaFuncSetAttribute(mma_gemm<128>, cudaFuncAttributeMaxDynamicSharedMemorySize, NSTG * STG128);
        cudaFuncSetAttribute(mma_gemm<64>,  cudaFuncAttributeMaxDynamicSharedMemorySize, NSTG * STG64);
        cudaFuncSetAttribute(flash_attn, cudaFuncAttributeMaxDynamicSharedMemorySize, FA_SMEM);
        cudaStreamCreateWithFlags(&s1, cudaStreamNonBlocking);
        cudaStreamCreateWithFlags(&s2, cudaStreamNonBlocking);
        cudaEventCreateWithFlags(&e0, cudaEventDisableTiming);
        cudaEventCreateWithFlags(&e1, cudaEventDisableTiming);
        cudaEventCreateWithFlags(&e2, cudaEventDisableTiming);
        s_init = true;
    }

    const float* cur_raw  = (const float*)d_in[0];
    const float* ctx_raw  = (const float*)d_in[1];
    const float* pre_raw  = (const float*)d_in[2];
    const int*   ctx_mask = (const int*)d_in[3];
    const int*   utt_mask = (const int*)d_in[4];
    const float* norm_W   = (const float*)d_in[5];
    const float* norm_b   = (const float*)d_in[6];
    const float* norm_g   = (const float*)d_in[7];
    const float* norm_be  = (const float*)d_in[8];
    const float* Wq = (const float*)d_in[9];
    const float* bq = (const float*)d_in[10];
    const float* Wk = (const float*)d_in[11];
    const float* bk = (const float*)d_in[12];
    const float* Wv = (const float*)d_in[13];
    const float* bv = (const float*)d_in[14];
    const float* Wo = (const float*)d_in[15];
    const float* bo = (const float*)d_in[16];
    const float* ln_g = (const float*)d_in[17];
    const float* ln_b = (const float*)d_in[18];
    const float* W1 = (const float*)d_in[19];
    const float* b1 = (const float*)d_in[20];
    const float* W2 = (const float*)d_in[21];
    const float* b2 = (const float*)d_in[22];

    float* out  = (float*)d_out;
    float* cur_out   = out;
    float* slots_out = out + (long long)BB * LU * DD;

    float* fea_cur   = sym<float>(g_fea_cur);
    float* fea_ctx   = sym<float>(g_fea_ctx);
    float* fea_slots = sym<float>(g_fea_slots);
    float* cur_attn  = sym<float>(g_cur_attn);
    float* proj1 = sym<float>(g_proj1);
    float* va = sym<float>(g_va);
    float* bkv0 = sym<float>(g_bkv0);
    float* bkv1 = sym<float>(g_bkv1);

    bf16 *wn_h = sym<bf16>(g_wn_h), *wn_l = sym<bf16>(g_wn_l);
    bf16 *wq_h = sym<bf16>(g_wq_h), *wq_l = sym<bf16>(g_wq_l);
    bf16 *wkv0_h = sym<bf16>(g_wkv0_h), *wkv0_l = sym<bf16>(g_wkv0_l);
    bf16 *wkv1_h = sym<bf16>(g_wkv1_h), *wkv1_l = sym<bf16>(g_wkv1_l);
    bf16 *wo_h = sym<bf16>(g_wo_h), *wo_l = sym<bf16>(g_wo_l);
    bf16 *w1_h = sym<bf16>(g_w1_h), *w1_l = sym<bf16>(g_w1_l);
    bf16 *w2_h = sym<bf16>(g_w2_h), *w2_l = sym<bf16>(g_w2_l);
    bf16 *xcur_h = sym<bf16>(g_xcur_h), *xcur_l = sym<bf16>(g_xcur_l);
    bf16 *xctx_h = sym<bf16>(g_xctx_h), *xctx_l = sym<bf16>(g_xctx_l);
    bf16 *xpre_h = sym<bf16>(g_xpre_h), *xpre_l = sym<bf16>(g_xpre_l);
    bf16 *fc_h = sym<bf16>(g_fc_h), *fc_l = sym<bf16>(g_fc_l);
    bf16 *fx_h = sym<bf16>(g_fx_h), *fx_l = sym<bf16>(g_fx_l);
    bf16 *fs_h = sym<bf16>(g_fs_h), *fs_l = sym<bf16>(g_fs_l);
    bf16 *lnb_h = sym<bf16>(g_lnb_h), *lnb_l = sym<bf16>(g_lnb_l);
    bf16 *ffh_h = sym<bf16>(g_ffh_h), *ffh_l = sym<bf16>(g_ffh_l);
    bf16 *a0_h = sym<bf16>(g_a0_h), *a0_l = sym<bf16>(g_a0_l);
    bf16 *a1_h = sym<bf16>(g_a1_h), *a1_l = sym<bf16>(g_a1_l);
    bf16 *co_h = sym<bf16>(g_co_h), *co_l = sym<bf16>(g_co_l);
    bf16 *q0h = sym<bf16>(g_q0h), *q0l = sym<bf16>(g_q0l);
    bf16 *kv0h = sym<bf16>(g_kv0h), *kv0l = sym<bf16>(g_kv0l);
    bf16 *q1h = sym<bf16>(g_q1h), *q1l = sym<bf16>(g_q1l);
    bf16 *kv1h = sym<bf16>(g_kv1h), *kv1l = sym<bf16>(g_kv1l);

    const int DxD = DD * DD;
    const int N2 = 2 * DD;

    // ---- packed biases
    cudaMemcpyAsync(bkv0,      bk,      DD * 4, cudaMemcpyDeviceToDevice, 0);
    cudaMemcpyAsync(bkv0 + DD, bv,      DD * 4, cudaMemcpyDeviceToDevice, 0);
    cudaMemcpyAsync(bkv1,      bk + DD, DD * 4, cudaMemcpyDeviceToDevice, 0);
    cudaMemcpyAsync(bkv1 + DD, bv + DD, DD * 4, cudaMemcpyDeviceToDevice, 0);

    // ---- one launch for ALL fp32->hi/lo conversions (with KV weight packing)
    {
        ConvArgs ca;
        const float* xs[NSEG] = { norm_W, Wq, Wo, W1, W2,
                                  Wk, Wv, Wk + DxD, Wv + DxD,
                                  cur_raw, ctx_raw, pre_raw };
        bf16* hs[NSEG] = { wn_h, wq_h, wo_h, w1_h, w2_h,
                           wkv0_h, wkv0_h, wkv1_h, wkv1_h,
                           xcur_h, xctx_h, xpre_h };
        bf16* ls[NSEG] = { wn_l, wq_l, wo_l, w1_l, w2_l,
                           wkv0_l, wkv0_l, wkv1_l, wkv1_l,
                           xcur_l, xctx_l, xpre_l };
        int ns[NSEG] = { 3*DxD/4, 2*DxD/4, 2*DxD/4, 2*DD*DFF/4, 2*DFF*DD/4,
                         DxD/4, DxD/4, DxD/4, DxD/4,
                         BB*LU*DD/4, BB*LC*DD/4, SS*BB*DD/4 };
        int ld4[NSEG] = { 192, 192, 192, 192, 192, 384, 384, 384, 384, 192, 192, 192 };
        int co4[NSEG] = { 0, 0, 0, 0, 0, 0, 192, 0, 192, 0, 0, 0 };
        for (int i = 0; i < NSEG; i++) {
            ca.x[i]=xs[i]; ca.h[i]=hs[i]; ca.l[i]=ls[i];
            ca.n4[i]=ns[i]; ca.ldo4[i]=ld4[i]; ca.coff4[i]=co4[i];
        }
        conv_split_multi<<<dim3(128, NSEG), 256>>>(ca);
    }
    cudaEventRecord(e0, 0);
    cudaStreamWaitEvent(s1, e0, 0);
    cudaStreamWaitEvent(s2, e0, 0);

    // ---- s1: cur chain (norm -> LN -> Q0)
    run_lin_s(s1, xcur_h, xcur_l, wn_h, wn_l, fea_cur, BB * LU, DD, DD, norm_b, nullptr, 0);
    ln_warp<<<BB * LU / 8, 256, 0, s1>>>(fea_cur, fea_cur, fc_h, fc_l, norm_g, norm_be);
    run_lin_s(s1, fc_h, fc_l, wq_h, wq_l, nullptr, BB * LU, DD, DD, bq, nullptr, 0, q0h, q0l);
    cudaEventRecord(e1, s1);

    // ---- s2: slots chain (norm -> LN -> Q1)
    run_lin_s(s2, xpre_h, xpre_l, wn_h + 2 * DxD, wn_l + 2 * DxD, fea_slots, SS * BB, DD, DD,
              norm_b + 2 * DD, nullptr, 0);
    ln_warp<<<SS * BB / 8, 256, 0, s2>>>(fea_slots, fea_slots, fs_h, fs_l,
                                         norm_g + 2 * DD, norm_be + 2 * DD);
    run_lin_s(s2, fs_h, fs_l, wq_h + DxD, wq_l + DxD, nullptr, SS * BB, DD, DD, bq + DD,
              nullptr, 0, q1h, q1l);
    cudaEventRecord(e2, s2);

    // ---- main: ctx chain (norm -> LN -> fused K0|V0)
    run_lin_s(0, xctx_h, xctx_l, wn_h + DxD, wn_l + DxD, fea_ctx, BB * LC, DD, DD,
              norm_b + DD, nullptr, 0);
    ln_warp<<<BB * LC / 8, 256>>>(fea_ctx, nullptr, fx_h, fx_l, norm_g + DD, norm_be + DD);
    run_lin_s(0, fx_h, fx_l, wkv0_h, wkv0_l, nullptr, BB * LC, N2, DD, bkv0, nullptr, 0,
              kv0h, kv0l);

    cudaStreamWaitEvent(0, e1, 0);

    // ---- stage B (main)
    flash_attn<<<BB * HH, 256, FA_SMEM>>>(q0h, q0l, kv0h, kv0l, kv0h + DD, kv0l + DD,
                                          ctx_mask, a0_h, a0_l, LU, LC, LU, 1, LU, N2, 0.125f);
    run_lin_s(0, a0_h, a0_l, wo_h, wo_l, cur_attn, BB * LU, DD, DD, bo, fea_cur, 0);
    ln_warp<<<BB * LU / 8, 256>>>(cur_attn, nullptr, lnb_h, lnb_l, ln_g, ln_b);
    run_lin_s(0, lnb_h, lnb_l, w1_h, w1_l, nullptr, BB * LU, DFF, DD, b1, nullptr, 1, ffh_h, ffh_l);
    run_lin_s(0, ffh_h, ffh_l, w2_h, w2_l, cur_out, BB * LU, DD, DFF, b2, cur_attn, 0, co_h, co_l);

    // ---- stage C (main): fused K1|V1
    run_lin_s(0, co_h, co_l, wkv1_h, wkv1_l, nullptr, BB * LU, N2, DD, bkv1, nullptr, 0,
              kv1h, kv1l);

    cudaStreamWaitEvent(0, e2, 0);

    flash_attn<<<BB * HH, 256, FA_SMEM>>>(q1h, q1l, kv1h, kv1l, kv1h + DD, kv1l + DD,
                                          utt_mask, a1_h, a1_l, SS, LU, 1, BB, SS, N2, 0.125f);

    run_lin_s(0, a1_h, a1_l, wo_h + DxD, wo_l + DxD, proj1, BB * SS, DD, DD, bo + DD, nullptr, 0);
    va_kernel<<<(SS * BB * DD + 255) / 256, 256>>>(fea_slots, proj1, va);

    ln_warp<<<SS * BB / 8, 256>>>(va, nullptr, lnb_h, lnb_l, ln_g + DD, ln_b + DD);
    run_lin_s(0, lnb_h, lnb_l, w1_h + DD * DFF, w1_l + DD * DFF, nullptr, SS * BB, DFF, DD,
              b1 + DFF, nullptr, 1, ffh_h, ffh_l);
    run_lin_s(0, ffh_h, ffh_l, w2_h + DFF * DD, w2_l + DFF * DD, slots_out, SS * BB, DD, DFF,
              b2 + DD, va, 0);
}

// round 10
// speedup vs baseline: 1.2859x; 1.2859x over previous
#include <cuda_runtime.h>
#include <cuda_fp16.h>
#include <cstdint>

// Problem dims
#define BB   32
#define LU   128
#define LC   512
#define SS   30
#define DD   768
#define HH   12
#define DK   64
#define DFF  1152

typedef __half  f16;
typedef __half2 f162;

// ---------------- fp32 scratch ----------------------------------------------
__device__ __align__(256) float g_fea_cur[BB*LU*DD];
__device__ __align__(256) float g_fea_ctx[BB*LC*DD];
__device__ __align__(256) float g_fea_slots[SS*BB*DD];
__device__ __align__(256) float g_cur_attn[BB*LU*DD];
__device__ __align__(256) float g_proj1[BB*SS*DD];
__device__ __align__(256) float g_va[SS*BB*DD];
__device__ __align__(256) float g_bkv0[2*DD];
__device__ __align__(256) float g_bkv1[2*DD];

// ---------------- f16 scratch: weights single, activations hi/lo ------------
__device__ __align__(256) f16 g_wn_h[3*DD*DD];
__device__ __align__(256) f16 g_wq_h[2*DD*DD];
__device__ __align__(256) f16 g_wkv0_h[DD*2*DD];
__device__ __align__(256) f16 g_wkv1_h[DD*2*DD];
__device__ __align__(256) f16 g_wo_h[2*DD*DD];
__device__ __align__(256) f16 g_w1_h[2*DD*DFF];
__device__ __align__(256) f16 g_w2_h[2*DFF*DD];
__device__ __align__(256) f16 g_xcur_h[BB*LU*DD], g_xcur_l[BB*LU*DD];
__device__ __align__(256) f16 g_xctx_h[BB*LC*DD], g_xctx_l[BB*LC*DD];
__device__ __align__(256) f16 g_xpre_h[SS*BB*DD], g_xpre_l[SS*BB*DD];
__device__ __align__(256) f16 g_fc_h[BB*LU*DD],  g_fc_l[BB*LU*DD];
__device__ __align__(256) f16 g_fx_h[BB*LC*DD],  g_fx_l[BB*LC*DD];
__device__ __align__(256) f16 g_fs_h[SS*BB*DD],  g_fs_l[SS*BB*DD];
__device__ __align__(256) f16 g_lnb_h[BB*LU*DD], g_lnb_l[BB*LU*DD];
__device__ __align__(256) f16 g_ffh_h[BB*LU*DFF], g_ffh_l[BB*LU*DFF];
__device__ __align__(256) f16 g_a0_h[BB*LU*DD],  g_a0_l[BB*LU*DD];
__device__ __align__(256) f16 g_a1_h[BB*SS*DD],  g_a1_l[BB*SS*DD];
__device__ __align__(256) f16 g_co_h[BB*LU*DD],  g_co_l[BB*LU*DD];
__device__ __align__(256) f16 g_q0h[BB*LU*DD], g_q0l[BB*LU*DD];
__device__ __align__(256) f16 g_kv0h[BB*LC*2*DD], g_kv0l[BB*LC*2*DD];
__device__ __align__(256) f16 g_q1h[SS*BB*DD], g_q1l[SS*BB*DD];
__device__ __align__(256) f16 g_kv1h[BB*LU*2*DD], g_kv1l[BB*LU*2*DD];

// =================== helpers ================================================
__device__ __forceinline__ uint32_t smem_u32(const void* p) {
    uint32_t a;
    asm("{ .reg .u64 t; cvta.to.shared.u64 t, %1; cvt.u32.u64 %0, t; }" : "=r"(a) : "l"(p));
    return a;
}
__device__ __forceinline__ void ldm_x4(uint32_t* r, uint32_t addr) {
    asm volatile("ldmatrix.sync.aligned.m8n8.x4.shared.b16 {%0,%1,%2,%3}, [%4];"
                 : "=r"(r[0]), "=r"(r[1]), "=r"(r[2]), "=r"(r[3]) : "r"(addr));
}
__device__ __forceinline__ void ldm_x4_t(uint32_t* r, uint32_t addr) {
    asm volatile("ldmatrix.sync.aligned.m8n8.x4.trans.shared.b16 {%0,%1,%2,%3}, [%4];"
                 : "=r"(r[0]), "=r"(r[1]), "=r"(r[2]), "=r"(r[3]) : "r"(addr));
}
__device__ __forceinline__ void mma_f16(float* c, const uint32_t* a, const uint32_t* b) {
    asm volatile("mma.sync.aligned.m16n8k16.row.col.f32.f16.f16.f32 "
                 "{%0,%1,%2,%3}, {%4,%5,%6,%7}, {%8,%9}, {%0,%1,%2,%3};"
                 : "+f"(c[0]), "+f"(c[1]), "+f"(c[2]), "+f"(c[3])
                 : "r"(a[0]), "r"(a[1]), "r"(a[2]), "r"(a[3]), "r"(b[0]), "r"(b[1]));
}
__device__ __forceinline__ void mma_f16_b(float* c, const uint32_t* a, uint32_t b0, uint32_t b1) {
    asm volatile("mma.sync.aligned.m16n8k16.row.col.f32.f16.f16.f32 "
                 "{%0,%1,%2,%3}, {%4,%5,%6,%7}, {%8,%9}, {%0,%1,%2,%3};"
                 : "+f"(c[0]), "+f"(c[1]), "+f"(c[2]), "+f"(c[3])
                 : "r"(a[0]), "r"(a[1]), "r"(a[2]), "r"(a[3]), "r"(b0), "r"(b1));
}
__device__ __forceinline__ void split2h(float x, float y, f162& h, f162& l) {
    f16 hx = __float2half_rn(x), hy = __float2half_rn(y);
    h = __halves2half2(hx, hy);
    l = __halves2half2(__float2half_rn(x - __half2float(hx)),
                       __float2half_rn(y - __half2float(hy)));
}

// --------- merged fp32 -> f16 converter; lo==nullptr => hi-only -------------
#define NSEG 12
struct ConvArgs {
    const float* x[NSEG];
    f16* h[NSEG];
    f16* l[NSEG];
    int n4[NSEG];
    int ldo4[NSEG];
    int coff4[NSEG];
};
__global__ __launch_bounds__(256)
void conv_split_multi(ConvArgs a)
{
    int s = blockIdx.y;
    int n4 = a.n4[s];
    const float* x = a.x[s];
    f16* h = a.h[s];
    f16* l = a.l[s];
    int ldo4 = a.ldo4[s], coff4 = a.coff4[s];
    int stride = gridDim.x * 256;
    for (int i = blockIdx.x * 256 + threadIdx.x; i < n4; i += stride) {
        float4 v = ((const float4*)x)[i];
        f162 h01, l01, h23, l23;
        split2h(v.x, v.y, h01, l01);
        split2h(v.z, v.w, h23, l23);
        int o4 = (i / 192) * ldo4 + coff4 + (i % 192);
        ((f162*)h)[2*o4]   = h01; ((f162*)h)[2*o4+1] = h23;
        if (l) { ((f162*)l)[2*o4] = l01; ((f162*)l)[2*o4+1] = l23; }
    }
}

// ====== split-f16 HMMA GEMM (A hi/lo, W single), 2-stage cp.async ===========
#define A_STRIDE 80
#define B_STRIDE 272
#define KC 32
#define B_TILE 8704            // 32 * 272

template<int MT>
__device__ __forceinline__ void stage_load(
    uint32_t stg, const f16* __restrict__ Ah, const f16* __restrict__ Al,
    const f16* __restrict__ Bh,
    int m0, int n0, int kc0, int M, int N, int K, int tid)
{
    constexpr int SA = MT * A_STRIDE;
    #pragma unroll
    for (int i = 0; i < MT / 64; i++) {
        int ca = tid + (i << 8);
        int r = ca >> 2, seg = ca & 3;
        int m = m0 + r;
        uint32_t dst = stg + (uint32_t)(r * A_STRIDE + seg * 16);
        int sz = (m < M) ? 16 : 0;
        size_t so = (size_t)m * K + kc0 + seg * 8;
        asm volatile("cp.async.cg.shared.global [%0], [%1], 16, %2;"
                     :: "r"(dst), "l"(Ah + so), "r"(sz));
        asm volatile("cp.async.cg.shared.global [%0], [%1], 16, %2;"
                     :: "r"(dst + SA), "l"(Al + so), "r"(sz));
    }
    #pragma unroll
    for (int i = 0; i < 2; i++) {
        int cb = tid + (i << 8);
        int r = cb >> 4, seg = cb & 15;
        uint32_t dst = stg + (uint32_t)(2 * SA + r * B_STRIDE + seg * 16);
        size_t so = (size_t)(kc0 + r) * N + n0 + seg * 8;
        asm volatile("cp.async.cg.shared.global [%0], [%1], 16;"
                     :: "r"(dst), "l"(Bh + so));
    }
    asm volatile("cp.async.commit_group;");
}

template<int MT>
__global__ void __launch_bounds__(256)
mma_gemm(const f16* __restrict__ Ah, const f16* __restrict__ Al,
         const f16* __restrict__ Bh,
         float* __restrict__ C, int M, int N, int K,
         const float* __restrict__ bias, const float* __restrict__ res, int relu,
         f16* __restrict__ Ch, f16* __restrict__ Cl)
{
    constexpr int SA  = MT * A_STRIDE;
    constexpr int T_BH = 2 * SA;
    constexpr int TSTG = 2 * SA + B_TILE;
    constexpr int WM = (MT == 128) ? 4 : 2;
    constexpr int NP = (MT == 128) ? 4 : 2;

    extern __shared__ __align__(128) char smem[];
    const uint32_t sb = smem_u32(smem);
    const int tid = threadIdx.x;
    const int wid = tid >> 5, lane = tid & 31;
    const int m0 = blockIdx.y * MT, n0 = blockIdx.x * 128;
    const int mw = (wid % WM) * 32;
    const int nw = (wid / WM) * (NP * 16);

    float acc[2][NP * 2][4];
    #pragma unroll
    for (int i = 0; i < 2; i++)
        #pragma unroll
        for (int j = 0; j < NP * 2; j++)
            #pragma unroll
            for (int q = 0; q < 4; q++) acc[i][j][q] = 0.f;

    const int lsub = lane >> 3, lr = lane & 7;
    const uint32_t aOff = (uint32_t)((lr + (lsub & 1) * 8) * A_STRIDE + (lsub >> 1) * 16);
    const uint32_t bOff = (uint32_t)((lr + (lsub & 1) * 8) * B_STRIDE + (lsub >> 1) * 16);

    const int nc = K / KC;
    stage_load<MT>(sb, Ah, Al, Bh, m0, n0, 0, M, N, K, tid);

    for (int c = 0; c < nc; c++) {
        if (c + 1 < nc) {
            stage_load<MT>(sb + ((c + 1) & 1) * TSTG, Ah, Al, Bh,
                           m0, n0, (c + 1) * KC, M, N, K, tid);
            asm volatile("cp.async.wait_group 1;");
        } else {
            asm volatile("cp.async.wait_group 0;");
        }
        __syncthreads();

        const uint32_t st = sb + (c & 1) * TSTG;
        #pragma unroll
        for (int ks = 0; ks < KC; ks += 16) {
            uint32_t ah[2][4], al[2][4];
            #pragma unroll
            for (int mi = 0; mi < 2; mi++) {
                uint32_t off = aOff + (uint32_t)((mw + mi * 16) * A_STRIDE + ks * 2);
                ldm_x4(ah[mi], st + off);
                ldm_x4(al[mi], st + SA + off);
            }
            #pragma unroll
            for (int np = 0; np < NP; np++) {
                uint32_t off = bOff + (uint32_t)(ks * B_STRIDE + (nw + np * 16) * 2);
                uint32_t bh[4];
                ldm_x4_t(bh, st + T_BH + off);
                // product-outer: 4 distinct accumulators between revisits
                #pragma unroll
                for (int mi = 0; mi < 2; mi++)
                    #pragma unroll
                    for (int g2 = 0; g2 < 2; g2++)
                        mma_f16(acc[mi][np * 2 + g2], ah[mi], bh + g2 * 2);
                #pragma unroll
                for (int mi = 0; mi < 2; mi++)
                    #pragma unroll
                    for (int g2 = 0; g2 < 2; g2++)
                        mma_f16(acc[mi][np * 2 + g2], al[mi], bh + g2 * 2);
            }
        }
        __syncthreads();
    }

    // ---- epilogue
    const int qrow = lane >> 2, qcol = (lane & 3) * 2;
    #pragma unroll
    for (int mi = 0; mi < 2; mi++) {
        int r0 = m0 + mw + mi * 16 + qrow;
        #pragma unroll
        for (int ni = 0; ni < NP * 2; ni++) {
            int cidx = n0 + nw + ni * 8 + qcol;
            float* a = acc[mi][ni];
            #pragma unroll
            for (int hh = 0; hh < 2; hh++) {
                int r = r0 + hh * 8;
                if (r >= M) continue;
                float x = a[hh * 2 + 0] + bias[cidx];
                float y = a[hh * 2 + 1] + bias[cidx + 1];
                if (relu) { x = fmaxf(x, 0.f); y = fmaxf(y, 0.f); }
                if (res) {
                    const float2 rv = *(const float2*)&res[(size_t)r * N + cidx];
                    x += rv.x; y += rv.y;
                }
                if (C) {
                    float2 o; o.x = x; o.y = y;
                    *(float2*)&C[(size_t)r * N + cidx] = o;
                }
                if (Ch) {
                    f162 hv, lv;
                    split2h(x, y, hv, lv);
                    *(f162*)&Ch[(size_t)r * N + cidx] = hv;
                    *(f162*)&Cl[(size_t)r * N + cidx] = lv;
                }
            }
        }
    }
}

#define STG128 (2 * 128 * A_STRIDE + B_TILE)
#define STG64  (2 * 64  * A_STRIDE + B_TILE)

// =================== fused flash attention (split-f16 HMMA) =================
#define FA_STRIDE 144
#define FA_KH 0
#define FA_KL 18432
#define FA_VH 36864
#define FA_VL 55296
#define FA_MASK 73728
#define FA_SMEM (FA_MASK + 512)

__global__ void __launch_bounds__(256)
flash_attn(const f16* __restrict__ Qh, const f16* __restrict__ Ql,
           const f16* __restrict__ Kh, const f16* __restrict__ Kl,
           const f16* __restrict__ Vh, const f16* __restrict__ Vl,
           const int* __restrict__ mask,
           f16* __restrict__ Oh, f16* __restrict__ Ol,
           int Lq, int Lk, int qB, int qS, int oB, int kvld, float scale)
{
    extern __shared__ __align__(128) char smem[];
    const uint32_t sb = smem_u32(smem);
    const float* sbias = (const float*)(smem + FA_MASK);
    const int tid = threadIdx.x, wid = tid >> 5, lane = tid & 31;
    const int z = blockIdx.x, b = z / HH, h = z % HH;
    const int qt = lane >> 2, qc = (lane & 3) * 2;
    const int r0 = wid * 16 + qt, r1 = r0 + 8;
    const int colh = h * DK;

    uint32_t qhf[4][4], qlf[4][4];
    #pragma unroll
    for (int ks = 0; ks < 4; ks++) {
        #pragma unroll
        for (int p = 0; p < 4; p++) {
            int rr = (p & 1) ? r1 : r0;
            int kk = ks * 16 + qc + ((p >> 1) ? 8 : 0);
            if (rr < Lq) {
                size_t off = (size_t)(b * qB + rr * qS) * DD + colh + kk;
                qhf[ks][p] = *(const uint32_t*)(Qh + off);
                qlf[ks][p] = *(const uint32_t*)(Ql + off);
            } else { qhf[ks][p] = 0u; qlf[ks][p] = 0u; }
        }
    }

    float m0 = -1e30f, m1 = -1e30f, l0 = 0.f, l1 = 0.f;
    float oacc[8][4];
    #pragma unroll
    for (int j = 0; j < 8; j++)
        #pragma unroll
        for (int q = 0; q < 4; q++) oacc[j][q] = 0.f;

    const uint32_t ldOffK = (uint32_t)(((lane & 7) + ((lane >> 3) & 1) * 8) * FA_STRIDE
                                       + ((lane >> 4) * 8) * 2);

    const int nch = Lk / 128;
    for (int ch = 0; ch < nch; ch++) {
        const int k0g = ch * 128;
        #pragma unroll
        for (int i = 0; i < 4; i++) {
            int idx = tid + (i << 8);
            int r = idx >> 3, seg = idx & 7;
            size_t src = (size_t)(b * Lk + k0g + r) * kvld + colh + seg * 8;
            uint32_t dst = sb + (uint32_t)(r * FA_STRIDE + seg * 16);
            asm volatile("cp.async.cg.shared.global [%0], [%1], 16;" :: "r"(dst + FA_KH), "l"(Kh + src));
            asm volatile("cp.async.cg.shared.global [%0], [%1], 16;" :: "r"(dst + FA_KL), "l"(Kl + src));
            asm volatile("cp.async.cg.shared.global [%0], [%1], 16;" :: "r"(dst + FA_VH), "l"(Vh + src));
            asm volatile("cp.async.cg.shared.global [%0], [%1], 16;" :: "r"(dst + FA_VL), "l"(Vl + src));
        }
        asm volatile("cp.async.commit_group;");
        if (tid < 128)
            ((float*)(smem + FA_MASK))[tid] = mask[b * Lk + k0g + tid] ? 0.f : -1e9f;
        asm volatile("cp.async.wait_group 0;");
        __syncthreads();

        float sacc[16][4];
        #pragma unroll
        for (int j = 0; j < 16; j++)
            #pragma unroll
            for (int q = 0; q < 4; q++) sacc[j][q] = 0.f;

        #pragma unroll
        for (int ks = 0; ks < 4; ks++) {
            #pragma unroll
            for (int nt = 0; nt < 8; nt++) {
                uint32_t off = ldOffK + (uint32_t)(nt * 16 * FA_STRIDE + ks * 32);
                uint32_t kh4[4], kl4[4];
                ldm_x4(kh4, sb + FA_KH + off);
                ldm_x4(kl4, sb + FA_KL + off);
                #pragma unroll
                for (int sub = 0; sub < 2; sub++)
                    mma_f16_b(sacc[nt * 2 + sub], qhf[ks], kh4[sub], kh4[sub + 2]);
                #pragma unroll
                for (int sub = 0; sub < 2; sub++)
                    mma_f16_b(sacc[nt * 2 + sub], qhf[ks], kl4[sub], kl4[sub + 2]);
                #pragma unroll
                for (int sub = 0; sub < 2; sub++)
                    mma_f16_b(sacc[nt * 2 + sub], qlf[ks], kh4[sub], kh4[sub + 2]);
            }
        }

        float cm0 = -1e30f, cm1 = -1e30f;
        #pragma unroll
        for (int j = 0; j < 16; j++) {
            int kb = j * 8 + qc;
            float b0v = sbias[kb], b1v = sbias[kb + 1];
            sacc[j][0] = sacc[j][0] * scale + b0v;
            sacc[j][1] = sacc[j][1] * scale + b1v;
            sacc[j][2] = sacc[j][2] * scale + b0v;
            sacc[j][3] = sacc[j][3] * scale + b1v;
            cm0 = fmaxf(cm0, fmaxf(sacc[j][0], sacc[j][1]));
            cm1 = fmaxf(cm1, fmaxf(sacc[j][2], sacc[j][3]));
        }
        cm0 = fmaxf(cm0, __shfl_xor_sync(0xFFFFFFFFu, cm0, 1));
        cm0 = fmaxf(cm0, __shfl_xor_sync(0xFFFFFFFFu, cm0, 2));
        cm1 = fmaxf(cm1, __shfl_xor_sync(0xFFFFFFFFu, cm1, 1));
        cm1 = fmaxf(cm1, __shfl_xor_sync(0xFFFFFFFFu, cm1, 2));
        float nm0 = fmaxf(m0, cm0), nm1 = fmaxf(m1, cm1);
        float al0 = __expf(m0 - nm0), al1 = __expf(m1 - nm1);
        m0 = nm0; m1 = nm1;

        float ps0 = 0.f, ps1 = 0.f;
        #pragma unroll
        for (int j = 0; j < 16; j++) {
            float p0 = __expf(sacc[j][0] - nm0), p1 = __expf(sacc[j][1] - nm0);
            float p2 = __expf(sacc[j][2] - nm1), p3 = __expf(sacc[j][3] - nm1);
            ps0 += p0 + p1; ps1 += p2 + p3;
            sacc[j][0] = p0; sacc[j][1] = p1; sacc[j][2] = p2; sacc[j][3] = p3;
        }
        ps0 += __shfl_xor_sync(0xFFFFFFFFu, ps0, 1);
        ps0 += __shfl_xor_sync(0xFFFFFFFFu, ps0, 2);
        ps1 += __shfl_xor_sync(0xFFFFFFFFu, ps1, 1);
        ps1 += __shfl_xor_sync(0xFFFFFFFFu, ps1, 2);
        l0 = l0 * al0 + ps0; l1 = l1 * al1 + ps1;
        #pragma unroll
        for (int j = 0; j < 8; j++) {
            oacc[j][0] *= al0; oacc[j][1] *= al0;
            oacc[j][2] *= al1; oacc[j][3] *= al1;
        }

        #pragma unroll
        for (int kk = 0; kk < 8; kk++) {
            uint32_t ahp[4], alp[4];
            #pragma unroll
            for (int jj = 0; jj < 2; jj++) {
                const float* sp = sacc[2 * kk + jj];
                f162 h01, l01, h23, l23;
                split2h(sp[0], sp[1], h01, l01);
                split2h(sp[2], sp[3], h23, l23);
                ahp[jj * 2 + 0] = *(uint32_t*)&h01; ahp[jj * 2 + 1] = *(uint32_t*)&h23;
                alp[jj * 2 + 0] = *(uint32_t*)&l01; alp[jj * 2 + 1] = *(uint32_t*)&l23;
            }
            #pragma unroll
            for (int dt = 0; dt < 4; dt++) {
                uint32_t off = ldOffK + (uint32_t)(kk * 16 * FA_STRIDE + dt * 32);
                uint32_t vh4[4], vl4[4];
                ldm_x4_t(vh4, sb + FA_VH + off);
                ldm_x4_t(vl4, sb + FA_VL + off);
                #pragma unroll
                for (int sub = 0; sub < 2; sub++)
                    mma_f16_b(oacc[dt * 2 + sub], ahp, vh4[sub*2], vh4[sub*2+1]);
                #pragma unroll
                for (int sub = 0; sub < 2; sub++)
                    mma_f16_b(oacc[dt * 2 + sub], alp, vh4[sub*2], vh4[sub*2+1]);
                #pragma unroll
                for (int sub = 0; sub < 2; sub++)
                    mma_f16_b(oacc[dt * 2 + sub], ahp, vl4[sub*2], vl4[sub*2+1]);
            }
        }
        __syncthreads();
    }

    float inv0 = 1.f / l0, inv1 = 1.f / l1;
    #pragma unroll
    for (int j = 0; j < 8; j++) {
        int col = colh + j * 8 + qc;
        if (r0 < Lq) {
            f162 hv, lv;
            split2h(oacc[j][0] * inv0, oacc[j][1] * inv0, hv, lv);
            size_t off = (size_t)(b * oB + r0) * DD + col;
            *(f162*)(Oh + off) = hv; *(f162*)(Ol + off) = lv;
        }
        if (r1 < Lq) {
            f162 hv, lv;
            split2h(oacc[j][2] * inv1, oacc[j][3] * inv1, hv, lv);
            size_t off = (size_t)(b * oB + r1) * DD + col;
            *(f162*)(Oh + off) = hv; *(f162*)(Ol + off) = lv;
        }
    }
}

// ------- LayerNorm: warp per row, single pass, register resident ------------
__global__ __launch_bounds__(256)
void ln_warp(const float* __restrict__ x, float* __restrict__ y,
             f16* __restrict__ yh, f16* __restrict__ yl,
             const float* __restrict__ g, const float* __restrict__ be)
{
    const int lane = threadIdx.x & 31;
    const size_t row = (size_t)(blockIdx.x * 8) + (threadIdx.x >> 5);
    const float* xr = x + row * DD;

    float4 v[6];
    float s = 0.f, s2 = 0.f;
    #pragma unroll
    for (int i = 0; i < 6; i++) {
        v[i] = *(const float4*)&xr[i * 128 + lane * 4];
        s  += v[i].x + v[i].y + v[i].z + v[i].w;
        s2 += v[i].x * v[i].x + v[i].y * v[i].y + v[i].z * v[i].z + v[i].w * v[i].w;
    }
    #pragma unroll
    for (int o = 16; o > 0; o >>= 1) {
        s  += __shfl_xor_sync(0xFFFFFFFFu, s, o);
        s2 += __shfl_xor_sync(0xFFFFFFFFu, s2, o);
    }
    const float mean = s * (1.f / DD);
    const float var  = s2 * (1.f / DD) - mean * mean;
    const float rstd = rsqrtf(var + 1e-5f);

    #pragma unroll
    for (int i = 0; i < 6; i++) {
        int col = i * 128 + lane * 4;
        float4 gv = *(const float4*)&g[col];
        float4 bv = *(const float4*)&be[col];
        float4 o;
        o.x = (v[i].x - mean) * rstd * gv.x + bv.x;
        o.y = (v[i].y - mean) * rstd * gv.y + bv.y;
        o.z = (v[i].z - mean) * rstd * gv.z + bv.z;
        o.w = (v[i].w - mean) * rstd * gv.w + bv.w;
        if (y) *(float4*)&y[row * DD + col] = o;
        if (yh) {
            f162 h01, l01, h23, l23;
            split2h(o.x, o.y, h01, l01);
            split2h(o.z, o.w, h23, l23);
            *(f162*)&yh[row * DD + col]     = h01;
            *(f162*)&yh[row * DD + col + 2] = h23;
            *(f162*)&yl[row * DD + col]     = l01;
            *(f162*)&yl[row * DD + col + 2] = l23;
        }
    }
}

// ---------------- va = fea_slots[S,B,D] + proj1[B,S,D] transposed -----------
__global__ __launch_bounds__(256)
void va_kernel(const float* __restrict__ slots, const float* __restrict__ proj,
               float* __restrict__ va)
{
    int idx = blockIdx.x * 256 + threadIdx.x;
    if (idx >= SS * BB * DD) return;
    int d = idx % DD;
    int r = idx / DD;
    int s = r / BB, b = r % BB;
    va[idx] = slots[idx] + proj[((long long)b * SS + s) * DD + d];
}

// ---------------- host-side helpers ----------------------------------------
template<typename T>
static T* sym(const void* s) { void* p = nullptr; cudaGetSymbolAddress(&p, s); return (T*)p; }

static void run_lin_s(cudaStream_t st, const f16* Ah, const f16* Al, const f16* Wh,
                      float* C, int M, int N, int K,
                      const float* bias, const float* res, int relu,
                      f16* Ch = nullptr, f16* Cl = nullptr)
{
    int ctas128 = (N / 128) * ((M + 127) / 128);
    if (M <= 4096 && ctas128 < 232) {
        dim3 grid(N / 128, (M + 63) / 64);
        mma_gemm<64><<<grid, 256, 2 * STG64, st>>>(Ah, Al, Wh, C, M, N, K, bias, res, relu, Ch, Cl);
    } else {
        dim3 grid(N / 128, (M + 127) / 128);
        mma_gemm<128><<<grid, 256, 2 * STG128, st>>>(Ah, Al, Wh, C, M, N, K, bias, res, relu, Ch, Cl);
    }
}

extern "C" void kernel_launch(void* const* d_in, const int* in_sizes, int n_in,
                              void* d_out, int out_size)
{
    static bool s_init = false;
    static cudaStream_t s1, s2;
    static cudaEvent_t e0, e1, e2;
    if (!s_init) {
        cudaFuncSetAttribute(mma_gemm<128>, cudaFuncAttributeMaxDynamicSharedMemorySize, 2 * STG128);
        cudaFuncSetAttribute(mma_gemm<64>,  cudaFuncAttributeMaxDynamicSharedMemorySize, 2 * STG64);
        cudaFuncSetAttribute(flash_attn, cudaFuncAttributeMaxDynamicSharedMemorySize, FA_SMEM);
        cudaStreamCreateWithFlags(&s1, cudaStreamNonBlocking);
        cudaStreamCreateWithFlags(&s2, cudaStreamNonBlocking);
        cudaEventCreateWithFlags(&e0, cudaEventDisableTiming);
        cudaEventCreateWithFlags(&e1, cudaEventDisableTiming);
        cudaEventCreateWithFlags(&e2, cudaEventDisableTiming);
        s_init = true;
    }

    const float* cur_raw  = (const float*)d_in[0];
    const float* ctx_raw  = (const float*)d_in[1];
    const float* pre_raw  = (const float*)d_in[2];
    const int*   ctx_mask = (const int*)d_in[3];
    const int*   utt_mask = (const int*)d_in[4];
    const float* norm_W   = (const float*)d_in[5];
    const float* norm_b   = (const float*)d_in[6];
    const float* norm_g   = (const float*)d_in[7];
    const float* norm_be  = (const float*)d_in[8];
    const float* Wq = (const float*)d_in[9];
    const float* bq = (const float*)d_in[10];
    const float* Wk = (const float*)d_in[11];
    const float* bk = (const float*)d_in[12];
    const float* Wv = (const float*)d_in[13];
    const float* bv = (const float*)d_in[14];
    const float* Wo = (const float*)d_in[15];
    const float* bo = (const float*)d_in[16];
    const float* ln_g = (const float*)d_in[17];
    const float* ln_b = (const float*)d_in[18];
    const float* W1 = (const float*)d_in[19];
    const float* b1 = (const float*)d_in[20];
    const float* W2 = (const float*)d_in[21];
    const float* b2 = (const float*)d_in[22];

    float* out  = (float*)d_out;
    float* cur_out   = out;
    float* slots_out = out + (long long)BB * LU * DD;

    float* fea_cur   = sym<float>(g_fea_cur);
    float* fea_ctx   = sym<float>(g_fea_ctx);
    float* fea_slots = sym<float>(g_fea_slots);
    float* cur_attn  = sym<float>(g_cur_attn);
    float* proj1 = sym<float>(g_proj1);
    float* va = sym<float>(g_va);
    float* bkv0 = sym<float>(g_bkv0);
    float* bkv1 = sym<float>(g_bkv1);

    f16 *wn_h = sym<f16>(g_wn_h);
    f16 *wq_h = sym<f16>(g_wq_h);
    f16 *wkv0_h = sym<f16>(g_wkv0_h);
    f16 *wkv1_h = sym<f16>(g_wkv1_h);
    f16 *wo_h = sym<f16>(g_wo_h);
    f16 *w1_h = sym<f16>(g_w1_h);
    f16 *w2_h = sym<f16>(g_w2_h);
    f16 *xcur_h = sym<f16>(g_xcur_h), *xcur_l = sym<f16>(g_xcur_l);
    f16 *xctx_h = sym<f16>(g_xctx_h), *xctx_l = sym<f16>(g_xctx_l);
    f16 *xpre_h = sym<f16>(g_xpre_h), *xpre_l = sym<f16>(g_xpre_l);
    f16 *fc_h = sym<f16>(g_fc_h), *fc_l = sym<f16>(g_fc_l);
    f16 *fx_h = sym<f16>(g_fx_h), *fx_l = sym<f16>(g_fx_l);
    f16 *fs_h = sym<f16>(g_fs_h), *fs_l = sym<f16>(g_fs_l);
    f16 *lnb_h = sym<f16>(g_lnb_h), *lnb_l = sym<f16>(g_lnb_l);
    f16 *ffh_h = sym<f16>(g_ffh_h), *ffh_l = sym<f16>(g_ffh_l);
    f16 *a0_h = sym<f16>(g_a0_h), *a0_l = sym<f16>(g_a0_l);
    f16 *a1_h = sym<f16>(g_a1_h), *a1_l = sym<f16>(g_a1_l);
    f16 *co_h = sym<f16>(g_co_h), *co_l = sym<f16>(g_co_l);
    f16 *q0h = sym<f16>(g_q0h), *q0l = sym<f16>(g_q0l);
    f16 *kv0h = sym<f16>(g_kv0h), *kv0l = sym<f16>(g_kv0l);
    f16 *q1h = sym<f16>(g_q1h), *q1l = sym<f16>(g_q1l);
    f16 *kv1h = sym<f16>(g_kv1h), *kv1l = sym<f16>(g_kv1l);

    const int DxD = DD * DD;
    const int N2 = 2 * DD;

    // ---- packed biases
    cudaMemcpyAsync(bkv0,      bk,      DD * 4, cudaMemcpyDeviceToDevice, 0);
    cudaMemcpyAsync(bkv0 + DD, bv,      DD * 4, cudaMemcpyDeviceToDevice, 0);
    cudaMemcpyAsync(bkv1,      bk + DD, DD * 4, cudaMemcpyDeviceToDevice, 0);
    cudaMemcpyAsync(bkv1 + DD, bv + DD, DD * 4, cudaMemcpyDeviceToDevice, 0);

    // ---- one launch for ALL fp32->f16 conversions (weights hi-only)
    {
        ConvArgs ca;
        const float* xs[NSEG] = { norm_W, Wq, Wo, W1, W2,
                                  Wk, Wv, Wk + DxD, Wv + DxD,
                                  cur_raw, ctx_raw, pre_raw };
        f16* hs[NSEG] = { wn_h, wq_h, wo_h, w1_h, w2_h,
                          wkv0_h, wkv0_h, wkv1_h, wkv1_h,
                          xcur_h, xctx_h, xpre_h };
        f16* ls[NSEG] = { nullptr, nullptr, nullptr, nullptr, nullptr,
                          nullptr, nullptr, nullptr, nullptr,
                          xcur_l, xctx_l, xpre_l };
        int ns[NSEG] = { 3*DxD/4, 2*DxD/4, 2*DxD/4, 2*DD*DFF/4, 2*DFF*DD/4,
                         DxD/4, DxD/4, DxD/4, DxD/4,
                         BB*LU*DD/4, BB*LC*DD/4, SS*BB*DD/4 };
        int ld4[NSEG] = { 192, 192, 192, 192, 192, 384, 384, 384, 384, 192, 192, 192 };
        int co4[NSEG] = { 0, 0, 0, 0, 0, 0, 192, 0, 192, 0, 0, 0 };
        for (int i = 0; i < NSEG; i++) {
            ca.x[i]=xs[i]; ca.h[i]=hs[i]; ca.l[i]=ls[i];
            ca.n4[i]=ns[i]; ca.ldo4[i]=ld4[i]; ca.coff4[i]=co4[i];
        }
        conv_split_multi<<<dim3(128, NSEG), 256>>>(ca);
    }
    cudaEventRecord(e0, 0);
    cudaStreamWaitEvent(s1, e0, 0);
    cudaStreamWaitEvent(s2, e0, 0);

    // ---- s1: cur chain (norm -> LN -> Q0)
    run_lin_s(s1, xcur_h, xcur_l, wn_h, fea_cur, BB * LU, DD, DD, norm_b, nullptr, 0);
    ln_warp<<<BB * LU / 8, 256, 0, s1>>>(fea_cur, fea_cur, fc_h, fc_l, norm_g, norm_be);
    run_lin_s(s1, fc_h, fc_l, wq_h, nullptr, BB * LU, DD, DD, bq, nullptr, 0, q0h, q0l);
    cudaEventRecord(e1, s1);

    // ---- s2: slots chain (norm -> LN -> Q1)
    run_lin_s(s2, xpre_h, xpre_l, wn_h + 2 * DxD, fea_slots, SS * BB, DD, DD,
              norm_b + 2 * DD, nullptr, 0);
    ln_warp<<<SS * BB / 8, 256, 0, s2>>>(fea_slots, fea_slots, fs_h, fs_l,
                                         norm_g + 2 * DD, norm_be + 2 * DD);
    run_lin_s(s2, fs_h, fs_l, wq_h + DxD, nullptr, SS * BB, DD, DD, bq + DD,
              nullptr, 0, q1h, q1l);
    cudaEventRecord(e2, s2);

    // ---- main: ctx chain (norm -> LN -> fused K0|V0)
    run_lin_s(0, xctx_h, xctx_l, wn_h + DxD, fea_ctx, BB * LC, DD, DD,
              norm_b + DD, nullptr, 0);
    ln_warp<<<BB * LC / 8, 256>>>(fea_ctx, nullptr, fx_h, fx_l, norm_g + DD, norm_be + DD);
    run_lin_s(0, fx_h, fx_l, wkv0_h, nullptr, BB * LC, N2, DD, bkv0, nullptr, 0,
              kv0h, kv0l);

    cudaStreamWaitEvent(0, e1, 0);

    // ---- stage B (main)
    flash_attn<<<BB * HH, 256, FA_SMEM>>>(q0h, q0l, kv0h, kv0l, kv0h + DD, kv0l + DD,
                                          ctx_mask, a0_h, a0_l, LU, LC, LU, 1, LU, N2, 0.125f);
    run_lin_s(0, a0_h, a0_l, wo_h, cur_attn, BB * LU, DD, DD, bo, fea_cur, 0);
    ln_warp<<<BB * LU / 8, 256>>>(cur_attn, nullptr, lnb_h, lnb_l, ln_g, ln_b);
    run_lin_s(0, lnb_h, lnb_l, w1_h, nullptr, BB * LU, DFF, DD, b1, nullptr, 1, ffh_h, ffh_l);
    run_lin_s(0, ffh_h, ffh_l, w2_h, cur_out, BB * LU, DD, DFF, b2, cur_attn, 0, co_h, co_l);

    // ---- stage C (main): fused K1|V1
    run_lin_s(0, co_h, co_l, wkv1_h, nullptr, BB * LU, N2, DD, bkv1, nullptr, 0,
              kv1h, kv1l);

    cudaStreamWaitEvent(0, e2, 0);

    flash_attn<<<BB * HH, 256, FA_SMEM>>>(q1h, q1l, kv1h, kv1l, kv1h + DD, kv1l + DD,
                                          utt_mask, a1_h, a1_l, SS, LU, 1, BB, SS, N2, 0.125f);

    run_lin_s(0, a1_h, a1_l, wo_h + DxD, proj1, BB * SS, DD, DD, bo + DD, nullptr, 0);
    va_kernel<<<(SS * BB * DD + 255) / 256, 256>>>(fea_slots, proj1, va);

    ln_warp<<<SS * BB / 8, 256>>>(va, nullptr, lnb_h, lnb_l, ln_g + DD, ln_b + DD);
    run_lin_s(0, lnb_h, lnb_l, w1_h + DD * DFF, nullptr, SS * BB, DFF, DD,
              b1 + DFF, nullptr, 1, ffh_h, ffh_l);
    run_lin_s(0, ffh_h, ffh_l, w2_h + DFF * DD, slots_out, SS * BB, DD, DFF,
              b2 + DD, va, 0);
}

// round 11
// speedup vs baseline: 1.7013x; 1.3231x over previous
#include <cuda_runtime.h>
#include <cuda_fp16.h>
#include <cstdint>

// Problem dims
#define BB   32
#define LU   128
#define LC   512
#define SS   30
#define DD   768
#define HH   12
#define DK   64
#define DFF  1152

typedef __half  f16;
typedef __half2 f162;

// ---------------- fp32 scratch ----------------------------------------------
__device__ __align__(256) float g_fea_cur[BB*LU*DD];
__device__ __align__(256) float g_fea_ctx[BB*LC*DD];
__device__ __align__(256) float g_fea_slots[SS*BB*DD];
__device__ __align__(256) float g_cur_attn[BB*LU*DD];
__device__ __align__(256) float g_proj1[BB*SS*DD];
__device__ __align__(256) float g_va[SS*BB*DD];
__device__ __align__(256) float g_bkv0[2*DD];
__device__ __align__(256) float g_bkv1[2*DD];

// ---------------- f16 scratch (single precision everywhere) -----------------
__device__ __align__(256) f16 g_wn[3*DD*DD];
__device__ __align__(256) f16 g_wq[2*DD*DD];
__device__ __align__(256) f16 g_wkv0[DD*2*DD];
__device__ __align__(256) f16 g_wkv1[DD*2*DD];
__device__ __align__(256) f16 g_wo[2*DD*DD];
__device__ __align__(256) f16 g_w1[2*DD*DFF];
__device__ __align__(256) f16 g_w2[2*DFF*DD];
__device__ __align__(256) f16 g_xcur[BB*LU*DD];
__device__ __align__(256) f16 g_xctx[BB*LC*DD];
__device__ __align__(256) f16 g_xpre[SS*BB*DD];
__device__ __align__(256) f16 g_fc[BB*LU*DD];
__device__ __align__(256) f16 g_fx[BB*LC*DD];
__device__ __align__(256) f16 g_fs[SS*BB*DD];
__device__ __align__(256) f16 g_lnb[BB*LU*DD];
__device__ __align__(256) f16 g_ffh[BB*LU*DFF];
__device__ __align__(256) f16 g_a0[BB*LU*DD];
__device__ __align__(256) f16 g_a1[BB*SS*DD];
__device__ __align__(256) f16 g_co[BB*LU*DD];
__device__ __align__(256) f16 g_q0[BB*LU*DD];
__device__ __align__(256) f16 g_kv0[BB*LC*2*DD];
__device__ __align__(256) f16 g_q1[SS*BB*DD];
__device__ __align__(256) f16 g_kv1[BB*LU*2*DD];

// =================== helpers ================================================
__device__ __forceinline__ uint32_t smem_u32(const void* p) {
    uint32_t a;
    asm("{ .reg .u64 t; cvta.to.shared.u64 t, %1; cvt.u32.u64 %0, t; }" : "=r"(a) : "l"(p));
    return a;
}
__device__ __forceinline__ void ldm_x4(uint32_t* r, uint32_t addr) {
    asm volatile("ldmatrix.sync.aligned.m8n8.x4.shared.b16 {%0,%1,%2,%3}, [%4];"
                 : "=r"(r[0]), "=r"(r[1]), "=r"(r[2]), "=r"(r[3]) : "r"(addr));
}
__device__ __forceinline__ void ldm_x4_t(uint32_t* r, uint32_t addr) {
    asm volatile("ldmatrix.sync.aligned.m8n8.x4.trans.shared.b16 {%0,%1,%2,%3}, [%4];"
                 : "=r"(r[0]), "=r"(r[1]), "=r"(r[2]), "=r"(r[3]) : "r"(addr));
}
__device__ __forceinline__ void mma_f16(float* c, const uint32_t* a, const uint32_t* b) {
    asm volatile("mma.sync.aligned.m16n8k16.row.col.f32.f16.f16.f32 "
                 "{%0,%1,%2,%3}, {%4,%5,%6,%7}, {%8,%9}, {%0,%1,%2,%3};"
                 : "+f"(c[0]), "+f"(c[1]), "+f"(c[2]), "+f"(c[3])
                 : "r"(a[0]), "r"(a[1]), "r"(a[2]), "r"(a[3]), "r"(b[0]), "r"(b[1]));
}
__device__ __forceinline__ void mma_f16_b(float* c, const uint32_t* a, uint32_t b0, uint32_t b1) {
    asm volatile("mma.sync.aligned.m16n8k16.row.col.f32.f16.f16.f32 "
                 "{%0,%1,%2,%3}, {%4,%5,%6,%7}, {%8,%9}, {%0,%1,%2,%3};"
                 : "+f"(c[0]), "+f"(c[1]), "+f"(c[2]), "+f"(c[3])
                 : "r"(a[0]), "r"(a[1]), "r"(a[2]), "r"(a[3]), "r"(b0), "r"(b1));
}
__device__ __forceinline__ void split2h(float x, float y, f162& h, f162& l) {
    f16 hx = __float2half_rn(x), hy = __float2half_rn(y);
    h = __halves2half2(hx, hy);
    l = __halves2half2(__float2half_rn(x - __half2float(hx)),
                       __float2half_rn(y - __half2float(hy)));
}

// --------- merged fp32 -> f16 converter, with column packing ----------------
#define NSEG 12
struct ConvArgs {
    const float* x[NSEG];
    f16* h[NSEG];
    int n4[NSEG];
    int ldo4[NSEG];
    int coff4[NSEG];
};
__global__ __launch_bounds__(256)
void conv_multi(ConvArgs a)
{
    int s = blockIdx.y;
    int n4 = a.n4[s];
    const float* x = a.x[s];
    f16* h = a.h[s];
    int ldo4 = a.ldo4[s], coff4 = a.coff4[s];
    int stride = gridDim.x * 256;
    for (int i = blockIdx.x * 256 + threadIdx.x; i < n4; i += stride) {
        float4 v = ((const float4*)x)[i];
        f162 h01 = __halves2half2(__float2half_rn(v.x), __float2half_rn(v.y));
        f162 h23 = __halves2half2(__float2half_rn(v.z), __float2half_rn(v.w));
        int o4 = (i / 192) * ldo4 + coff4 + (i % 192);
        ((f162*)h)[2*o4]   = h01;
        ((f162*)h)[2*o4+1] = h23;
    }
}

// ========= single-f16 HMMA GEMM, 2-stage cp.async double-buffered ===========
#define A_STRIDE 80
#define B_STRIDE 272
#define KC 32
#define B_TILE 8704            // 32 * 272

template<int MT>
__device__ __forceinline__ void stage_load(
    uint32_t stg, const f16* __restrict__ A, const f16* __restrict__ B,
    int m0, int n0, int kc0, int M, int N, int K, int tid)
{
    constexpr int SA = MT * A_STRIDE;
    #pragma unroll
    for (int i = 0; i < MT / 64; i++) {
        int ca = tid + (i << 8);
        int r = ca >> 2, seg = ca & 3;
        int m = m0 + r;
        uint32_t dst = stg + (uint32_t)(r * A_STRIDE + seg * 16);
        int sz = (m < M) ? 16 : 0;
        size_t so = (size_t)m * K + kc0 + seg * 8;
        asm volatile("cp.async.cg.shared.global [%0], [%1], 16, %2;"
                     :: "r"(dst), "l"(A + so), "r"(sz));
    }
    #pragma unroll
    for (int i = 0; i < 2; i++) {
        int cb = tid + (i << 8);
        int r = cb >> 4, seg = cb & 15;
        uint32_t dst = stg + (uint32_t)(SA + r * B_STRIDE + seg * 16);
        size_t so = (size_t)(kc0 + r) * N + n0 + seg * 8;
        asm volatile("cp.async.cg.shared.global [%0], [%1], 16;"
                     :: "r"(dst), "l"(B + so));
    }
    asm volatile("cp.async.commit_group;");
}

template<int MT>
__global__ void __launch_bounds__(256, 3)
mma_gemm(const f16* __restrict__ A, const f16* __restrict__ B,
         float* __restrict__ C, int M, int N, int K,
         const float* __restrict__ bias, const float* __restrict__ res, int relu,
         f16* __restrict__ Ch)
{
    constexpr int SA  = MT * A_STRIDE;
    constexpr int TSTG = SA + B_TILE;
    constexpr int WM = (MT == 128) ? 4 : 2;
    constexpr int NP = (MT == 128) ? 4 : 2;

    extern __shared__ __align__(128) char smem[];
    const uint32_t sb = smem_u32(smem);
    const int tid = threadIdx.x;
    const int wid = tid >> 5, lane = tid & 31;
    const int m0 = blockIdx.y * MT, n0 = blockIdx.x * 128;
    const int mw = (wid % WM) * 32;
    const int nw = (wid / WM) * (NP * 16);

    float acc[2][NP * 2][4];
    #pragma unroll
    for (int i = 0; i < 2; i++)
        #pragma unroll
        for (int j = 0; j < NP * 2; j++)
            #pragma unroll
            for (int q = 0; q < 4; q++) acc[i][j][q] = 0.f;

    const int lsub = lane >> 3, lr = lane & 7;
    const uint32_t aOff = (uint32_t)((lr + (lsub & 1) * 8) * A_STRIDE + (lsub >> 1) * 16);
    const uint32_t bOff = (uint32_t)((lr + (lsub & 1) * 8) * B_STRIDE + (lsub >> 1) * 16);

    const int nc = K / KC;
    stage_load<MT>(sb, A, B, m0, n0, 0, M, N, K, tid);

    for (int c = 0; c < nc; c++) {
        if (c + 1 < nc) {
            stage_load<MT>(sb + ((c + 1) & 1) * TSTG, A, B,
                           m0, n0, (c + 1) * KC, M, N, K, tid);
            asm volatile("cp.async.wait_group 1;");
        } else {
            asm volatile("cp.async.wait_group 0;");
        }
        __syncthreads();

        const uint32_t st = sb + (c & 1) * TSTG;
        #pragma unroll
        for (int ks = 0; ks < KC; ks += 16) {
            uint32_t ah[2][4];
            #pragma unroll
            for (int mi = 0; mi < 2; mi++) {
                uint32_t off = aOff + (uint32_t)((mw + mi * 16) * A_STRIDE + ks * 2);
                ldm_x4(ah[mi], st + off);
            }
            #pragma unroll
            for (int np = 0; np < NP; np++) {
                uint32_t off = bOff + (uint32_t)(ks * B_STRIDE + (nw + np * 16) * 2);
                uint32_t bh[4];
                ldm_x4_t(bh, st + SA + off);
                #pragma unroll
                for (int mi = 0; mi < 2; mi++)
                    #pragma unroll
                    for (int g2 = 0; g2 < 2; g2++)
                        mma_f16(acc[mi][np * 2 + g2], ah[mi], bh + g2 * 2);
            }
        }
        __syncthreads();
    }

    // ---- epilogue
    const int qrow = lane >> 2, qcol = (lane & 3) * 2;
    #pragma unroll
    for (int mi = 0; mi < 2; mi++) {
        int r0 = m0 + mw + mi * 16 + qrow;
        #pragma unroll
        for (int ni = 0; ni < NP * 2; ni++) {
            int cidx = n0 + nw + ni * 8 + qcol;
            float* a = acc[mi][ni];
            #pragma unroll
            for (int hh = 0; hh < 2; hh++) {
                int r = r0 + hh * 8;
                if (r >= M) continue;
                float x = a[hh * 2 + 0] + bias[cidx];
                float y = a[hh * 2 + 1] + bias[cidx + 1];
                if (relu) { x = fmaxf(x, 0.f); y = fmaxf(y, 0.f); }
                if (res) {
                    const float2 rv = *(const float2*)&res[(size_t)r * N + cidx];
                    x += rv.x; y += rv.y;
                }
                if (C) {
                    float2 o; o.x = x; o.y = y;
                    *(float2*)&C[(size_t)r * N + cidx] = o;
                }
                if (Ch) {
                    *(f162*)&Ch[(size_t)r * N + cidx] =
                        __halves2half2(__float2half_rn(x), __float2half_rn(y));
                }
            }
        }
    }
}

#define STG128 (128 * A_STRIDE + B_TILE)
#define STG64  (64  * A_STRIDE + B_TILE)

// ====== fused flash attention (single Q/K/V, P split in regs for PV) ========
#define FA_STRIDE 144
#define FA_K 0
#define FA_V 18432
#define FA_MASK 36864
#define FA_SMEM (FA_MASK + 512)

__global__ void __launch_bounds__(256)
flash_attn(const f16* __restrict__ Q, const f16* __restrict__ K,
           const f16* __restrict__ V, const int* __restrict__ mask,
           f16* __restrict__ O,
           int Lq, int Lk, int qB, int qS, int oB, int kvld, float scale)
{
    extern __shared__ __align__(128) char smem[];
    const uint32_t sb = smem_u32(smem);
    const float* sbias = (const float*)(smem + FA_MASK);
    const int tid = threadIdx.x, wid = tid >> 5, lane = tid & 31;
    const int z = blockIdx.x, b = z / HH, h = z % HH;
    const int qt = lane >> 2, qc = (lane & 3) * 2;
    const int r0 = wid * 16 + qt, r1 = r0 + 8;
    const int colh = h * DK;

    uint32_t qf[4][4];
    #pragma unroll
    for (int ks = 0; ks < 4; ks++) {
        #pragma unroll
        for (int p = 0; p < 4; p++) {
            int rr = (p & 1) ? r1 : r0;
            int kk = ks * 16 + qc + ((p >> 1) ? 8 : 0);
            if (rr < Lq) {
                size_t off = (size_t)(b * qB + rr * qS) * DD + colh + kk;
                qf[ks][p] = *(const uint32_t*)(Q + off);
            } else qf[ks][p] = 0u;
        }
    }

    float m0 = -1e30f, m1 = -1e30f, l0 = 0.f, l1 = 0.f;
    float oacc[8][4];
    #pragma unroll
    for (int j = 0; j < 8; j++)
        #pragma unroll
        for (int q = 0; q < 4; q++) oacc[j][q] = 0.f;

    const uint32_t ldOffK = (uint32_t)(((lane & 7) + ((lane >> 3) & 1) * 8) * FA_STRIDE
                                       + ((lane >> 4) * 8) * 2);

    const int nch = Lk / 128;
    for (int ch = 0; ch < nch; ch++) {
        const int k0g = ch * 128;
        #pragma unroll
        for (int i = 0; i < 4; i++) {
            int idx = tid + (i << 8);
            int r = idx >> 3, seg = idx & 7;
            size_t src = (size_t)(b * Lk + k0g + r) * kvld + colh + seg * 8;
            uint32_t dst = sb + (uint32_t)(r * FA_STRIDE + seg * 16);
            asm volatile("cp.async.cg.shared.global [%0], [%1], 16;" :: "r"(dst + FA_K), "l"(K + src));
            asm volatile("cp.async.cg.shared.global [%0], [%1], 16;" :: "r"(dst + FA_V), "l"(V + src));
        }
        asm volatile("cp.async.commit_group;");
        if (tid < 128)
            ((float*)(smem + FA_MASK))[tid] = mask[b * Lk + k0g + tid] ? 0.f : -1e9f;
        asm volatile("cp.async.wait_group 0;");
        __syncthreads();

        float sacc[16][4];
        #pragma unroll
        for (int j = 0; j < 16; j++)
            #pragma unroll
            for (int q = 0; q < 4; q++) sacc[j][q] = 0.f;

        #pragma unroll
        for (int ks = 0; ks < 4; ks++) {
            #pragma unroll
            for (int nt = 0; nt < 8; nt++) {
                uint32_t off = ldOffK + (uint32_t)(nt * 16 * FA_STRIDE + ks * 32);
                uint32_t kh4[4];
                ldm_x4(kh4, sb + FA_K + off);
                #pragma unroll
                for (int sub = 0; sub < 2; sub++)
                    mma_f16_b(sacc[nt * 2 + sub], qf[ks], kh4[sub], kh4[sub + 2]);
            }
        }

        float cm0 = -1e30f, cm1 = -1e30f;
        #pragma unroll
        for (int j = 0; j < 16; j++) {
            int kb = j * 8 + qc;
            float b0v = sbias[kb], b1v = sbias[kb + 1];
            sacc[j][0] = sacc[j][0] * scale + b0v;
            sacc[j][1] = sacc[j][1] * scale + b1v;
            sacc[j][2] = sacc[j][2] * scale + b0v;
            sacc[j][3] = sacc[j][3] * scale + b1v;
            cm0 = fmaxf(cm0, fmaxf(sacc[j][0], sacc[j][1]));
            cm1 = fmaxf(cm1, fmaxf(sacc[j][2], sacc[j][3]));
        }
        cm0 = fmaxf(cm0, __shfl_xor_sync(0xFFFFFFFFu, cm0, 1));
        cm0 = fmaxf(cm0, __shfl_xor_sync(0xFFFFFFFFu, cm0, 2));
        cm1 = fmaxf(cm1, __shfl_xor_sync(0xFFFFFFFFu, cm1, 1));
        cm1 = fmaxf(cm1, __shfl_xor_sync(0xFFFFFFFFu, cm1, 2));
        float nm0 = fmaxf(m0, cm0), nm1 = fmaxf(m1, cm1);
        float al0 = __expf(m0 - nm0), al1 = __expf(m1 - nm1);
        m0 = nm0; m1 = nm1;

        float ps0 = 0.f, ps1 = 0.f;
        #pragma unroll
        for (int j = 0; j < 16; j++) {
            float p0 = __expf(sacc[j][0] - nm0), p1 = __expf(sacc[j][1] - nm0);
            float p2 = __expf(sacc[j][2] - nm1), p3 = __expf(sacc[j][3] - nm1);
            ps0 += p0 + p1; ps1 += p2 + p3;
            sacc[j][0] = p0; sacc[j][1] = p1; sacc[j][2] = p2; sacc[j][3] = p3;
        }
        ps0 += __shfl_xor_sync(0xFFFFFFFFu, ps0, 1);
        ps0 += __shfl_xor_sync(0xFFFFFFFFu, ps0, 2);
        ps1 += __shfl_xor_sync(0xFFFFFFFFu, ps1, 1);
        ps1 += __shfl_xor_sync(0xFFFFFFFFu, ps1, 2);
        l0 = l0 * al0 + ps0; l1 = l1 * al1 + ps1;
        #pragma unroll
        for (int j = 0; j < 8; j++) {
            oacc[j][0] *= al0; oacc[j][1] *= al0;
            oacc[j][2] *= al1; oacc[j][3] *= al1;
        }

        // O += P @ V; P packed hi/lo on the fly (keeps P at ~fp32 fidelity)
        #pragma unroll
        for (int kk = 0; kk < 8; kk++) {
            uint32_t ahp[4], alp[4];
            #pragma unroll
            for (int jj = 0; jj < 2; jj++) {
                const float* sp = sacc[2 * kk + jj];
                f162 h01, l01, h23, l23;
                split2h(sp[0], sp[1], h01, l01);
                split2h(sp[2], sp[3], h23, l23);
                ahp[jj * 2 + 0] = *(uint32_t*)&h01; ahp[jj * 2 + 1] = *(uint32_t*)&h23;
                alp[jj * 2 + 0] = *(uint32_t*)&l01; alp[jj * 2 + 1] = *(uint32_t*)&l23;
            }
            #pragma unroll
            for (int dt = 0; dt < 4; dt++) {
                uint32_t off = ldOffK + (uint32_t)(kk * 16 * FA_STRIDE + dt * 32);
                uint32_t vh4[4];
                ldm_x4_t(vh4, sb + FA_V + off);
                #pragma unroll
                for (int sub = 0; sub < 2; sub++)
                    mma_f16_b(oacc[dt * 2 + sub], ahp, vh4[sub*2], vh4[sub*2+1]);
                #pragma unroll
                for (int sub = 0; sub < 2; sub++)
                    mma_f16_b(oacc[dt * 2 + sub], alp, vh4[sub*2], vh4[sub*2+1]);
            }
        }
        __syncthreads();
    }

    float inv0 = 1.f / l0, inv1 = 1.f / l1;
    #pragma unroll
    for (int j = 0; j < 8; j++) {
        int col = colh + j * 8 + qc;
        if (r0 < Lq) {
            size_t off = (size_t)(b * oB + r0) * DD + col;
            *(f162*)(O + off) = __halves2half2(__float2half_rn(oacc[j][0] * inv0),
                                               __float2half_rn(oacc[j][1] * inv0));
        }
        if (r1 < Lq) {
            size_t off = (size_t)(b * oB + r1) * DD + col;
            *(f162*)(O + off) = __halves2half2(__float2half_rn(oacc[j][2] * inv1),
                                               __float2half_rn(oacc[j][3] * inv1));
        }
    }
}

// ------- LayerNorm: warp per row, single pass, register resident ------------
__global__ __launch_bounds__(256)
void ln_warp(const float* __restrict__ x, float* __restrict__ y,
             f16* __restrict__ yh,
             const float* __restrict__ g, const float* __restrict__ be)
{
    const int lane = threadIdx.x & 31;
    const size_t row = (size_t)(blockIdx.x * 8) + (threadIdx.x >> 5);
    const float* xr = x + row * DD;

    float4 v[6];
    float s = 0.f, s2 = 0.f;
    #pragma unroll
    for (int i = 0; i < 6; i++) {
        v[i] = *(const float4*)&xr[i * 128 + lane * 4];
        s  += v[i].x + v[i].y + v[i].z + v[i].w;
        s2 += v[i].x * v[i].x + v[i].y * v[i].y + v[i].z * v[i].z + v[i].w * v[i].w;
    }
    #pragma unroll
    for (int o = 16; o > 0; o >>= 1) {
        s  += __shfl_xor_sync(0xFFFFFFFFu, s, o);
        s2 += __shfl_xor_sync(0xFFFFFFFFu, s2, o);
    }
    const float mean = s * (1.f / DD);
    const float var  = s2 * (1.f / DD) - mean * mean;
    const float rstd = rsqrtf(var + 1e-5f);

    #pragma unroll
    for (int i = 0; i < 6; i++) {
        int col = i * 128 + lane * 4;
        float4 gv = *(const float4*)&g[col];
        float4 bv = *(const float4*)&be[col];
        float4 o;
        o.x = (v[i].x - mean) * rstd * gv.x + bv.x;
        o.y = (v[i].y - mean) * rstd * gv.y + bv.y;
        o.z = (v[i].z - mean) * rstd * gv.z + bv.z;
        o.w = (v[i].w - mean) * rstd * gv.w + bv.w;
        if (y) *(float4*)&y[row * DD + col] = o;
        if (yh) {
            *(f162*)&yh[row * DD + col] =
                __halves2half2(__float2half_rn(o.x), __float2half_rn(o.y));
            *(f162*)&yh[row * DD + col + 2] =
                __halves2half2(__float2half_rn(o.z), __float2half_rn(o.w));
        }
    }
}

// ---------------- va = fea_slots[S,B,D] + proj1[B,S,D] transposed -----------
__global__ __launch_bounds__(256)
void va_kernel(const float* __restrict__ slots, const float* __restrict__ proj,
               float* __restrict__ va)
{
    int idx = blockIdx.x * 256 + threadIdx.x;
    if (idx >= SS * BB * DD) return;
    int d = idx % DD;
    int r = idx / DD;
    int s = r / BB, b = r % BB;
    va[idx] = slots[idx] + proj[((long long)b * SS + s) * DD + d];
}

// ---------------- host-side helpers ----------------------------------------
template<typename T>
static T* sym(const void* s) { void* p = nullptr; cudaGetSymbolAddress(&p, s); return (T*)p; }

static void run_lin_s(cudaStream_t st, const f16* A, const f16* W,
                      float* C, int M, int N, int K,
                      const float* bias, const float* res, int relu,
                      f16* Ch = nullptr)
{
    int ctas128 = (N / 128) * ((M + 127) / 128);
    if (M <= 4096 && ctas128 < 232) {
        dim3 grid(N / 128, (M + 63) / 64);
        mma_gemm<64><<<grid, 256, 2 * STG64, st>>>(A, W, C, M, N, K, bias, res, relu, Ch);
    } else {
        dim3 grid(N / 128, (M + 127) / 128);
        mma_gemm<128><<<grid, 256, 2 * STG128, st>>>(A, W, C, M, N, K, bias, res, relu, Ch);
    }
}

extern "C" void kernel_launch(void* const* d_in, const int* in_sizes, int n_in,
                              void* d_out, int out_size)
{
    static bool s_init = false;
    static cudaStream_t s1, s2;
    static cudaEvent_t e0, e1, e2;
    if (!s_init) {
        cudaFuncSetAttribute(mma_gemm<128>, cudaFuncAttributeMaxDynamicSharedMemorySize, 2 * STG128);
        cudaFuncSetAttribute(mma_gemm<64>,  cudaFuncAttributeMaxDynamicSharedMemorySize, 2 * STG64);
        cudaFuncSetAttribute(flash_attn, cudaFuncAttributeMaxDynamicSharedMemorySize, FA_SMEM);
        cudaStreamCreateWithFlags(&s1, cudaStreamNonBlocking);
        cudaStreamCreateWithFlags(&s2, cudaStreamNonBlocking);
        cudaEventCreateWithFlags(&e0, cudaEventDisableTiming);
        cudaEventCreateWithFlags(&e1, cudaEventDisableTiming);
        cudaEventCreateWithFlags(&e2, cudaEventDisableTiming);
        s_init = true;
    }

    const float* cur_raw  = (const float*)d_in[0];
    const float* ctx_raw  = (const float*)d_in[1];
    const float* pre_raw  = (const float*)d_in[2];
    const int*   ctx_mask = (const int*)d_in[3];
    const int*   utt_mask = (const int*)d_in[4];
    const float* norm_W   = (const float*)d_in[5];
    const float* norm_b   = (const float*)d_in[6];
    const float* norm_g   = (const float*)d_in[7];
    const float* norm_be  = (const float*)d_in[8];
    const float* Wq = (const float*)d_in[9];
    const float* bq = (const float*)d_in[10];
    const float* Wk = (const float*)d_in[11];
    const float* bk = (const float*)d_in[12];
    const float* Wv = (const float*)d_in[13];
    const float* bv = (const float*)d_in[14];
    const float* Wo = (const float*)d_in[15];
    const float* bo = (const float*)d_in[16];
    const float* ln_g = (const float*)d_in[17];
    const float* ln_b = (const float*)d_in[18];
    const float* W1 = (const float*)d_in[19];
    const float* b1 = (const float*)d_in[20];
    const float* W2 = (const float*)d_in[21];
    const float* b2 = (const float*)d_in[22];

    float* out  = (float*)d_out;
    float* cur_out   = out;
    float* slots_out = out + (long long)BB * LU * DD;

    float* fea_cur   = sym<float>(g_fea_cur);
    float* fea_ctx   = sym<float>(g_fea_ctx);
    float* fea_slots = sym<float>(g_fea_slots);
    float* cur_attn  = sym<float>(g_cur_attn);
    float* proj1 = sym<float>(g_proj1);
    float* va = sym<float>(g_va);
    float* bkv0 = sym<float>(g_bkv0);
    float* bkv1 = sym<float>(g_bkv1);

    f16 *wn = sym<f16>(g_wn);
    f16 *wq = sym<f16>(g_wq);
    f16 *wkv0 = sym<f16>(g_wkv0);
    f16 *wkv1 = sym<f16>(g_wkv1);
    f16 *wo = sym<f16>(g_wo);
    f16 *w1 = sym<f16>(g_w1);
    f16 *w2 = sym<f16>(g_w2);
    f16 *xcur = sym<f16>(g_xcur);
    f16 *xctx = sym<f16>(g_xctx);
    f16 *xpre = sym<f16>(g_xpre);
    f16 *fc = sym<f16>(g_fc);
    f16 *fx = sym<f16>(g_fx);
    f16 *fs = sym<f16>(g_fs);
    f16 *lnb = sym<f16>(g_lnb);
    f16 *ffh = sym<f16>(g_ffh);
    f16 *a0 = sym<f16>(g_a0);
    f16 *a1 = sym<f16>(g_a1);
    f16 *co = sym<f16>(g_co);
    f16 *q0 = sym<f16>(g_q0);
    f16 *kv0 = sym<f16>(g_kv0);
    f16 *q1 = sym<f16>(g_q1);
    f16 *kv1 = sym<f16>(g_kv1);

    const int DxD = DD * DD;
    const int N2 = 2 * DD;

    // ---- packed biases
    cudaMemcpyAsync(bkv0,      bk,      DD * 4, cudaMemcpyDeviceToDevice, 0);
    cudaMemcpyAsync(bkv0 + DD, bv,      DD * 4, cudaMemcpyDeviceToDevice, 0);
    cudaMemcpyAsync(bkv1,      bk + DD, DD * 4, cudaMemcpyDeviceToDevice, 0);
    cudaMemcpyAsync(bkv1 + DD, bv + DD, DD * 4, cudaMemcpyDeviceToDevice, 0);

    // ---- one launch for ALL fp32->f16 conversions (with KV weight packing)
    {
        ConvArgs ca;
        const float* xs[NSEG] = { norm_W, Wq, Wo, W1, W2,
                                  Wk, Wv, Wk + DxD, Wv + DxD,
                                  cur_raw, ctx_raw, pre_raw };
        f16* hs[NSEG] = { wn, wq, wo, w1, w2,
                          wkv0, wkv0, wkv1, wkv1,
                          xcur, xctx, xpre };
        int ns[NSEG] = { 3*DxD/4, 2*DxD/4, 2*DxD/4, 2*DD*DFF/4, 2*DFF*DD/4,
                         DxD/4, DxD/4, DxD/4, DxD/4,
                         BB*LU*DD/4, BB*LC*DD/4, SS*BB*DD/4 };
        int ld4[NSEG] = { 192, 192, 192, 192, 192, 384, 384, 384, 384, 192, 192, 192 };
        int co4[NSEG] = { 0, 0, 0, 0, 0, 0, 192, 0, 192, 0, 0, 0 };
        for (int i = 0; i < NSEG; i++) {
            ca.x[i]=xs[i]; ca.h[i]=hs[i];
            ca.n4[i]=ns[i]; ca.ldo4[i]=ld4[i]; ca.coff4[i]=co4[i];
        }
        conv_multi<<<dim3(128, NSEG), 256>>>(ca);
    }
    cudaEventRecord(e0, 0);
    cudaStreamWaitEvent(s1, e0, 0);
    cudaStreamWaitEvent(s2, e0, 0);

    // ---- s1: cur chain (norm -> LN -> Q0)
    run_lin_s(s1, xcur, wn, fea_cur, BB * LU, DD, DD, norm_b, nullptr, 0);
    ln_warp<<<BB * LU / 8, 256, 0, s1>>>(fea_cur, fea_cur, fc, norm_g, norm_be);
    run_lin_s(s1, fc, wq, nullptr, BB * LU, DD, DD, bq, nullptr, 0, q0);
    cudaEventRecord(e1, s1);

    // ---- s2: slots chain (norm -> LN -> Q1)
    run_lin_s(s2, xpre, wn + 2 * DxD, fea_slots, SS * BB, DD, DD,
              norm_b + 2 * DD, nullptr, 0);
    ln_warp<<<SS * BB / 8, 256, 0, s2>>>(fea_slots, fea_slots, fs,
                                         norm_g + 2 * DD, norm_be + 2 * DD);
    run_lin_s(s2, fs, wq + DxD, nullptr, SS * BB, DD, DD, bq + DD, nullptr, 0, q1);
    cudaEventRecord(e2, s2);

    // ---- main: ctx chain (norm -> LN -> fused K0|V0)
    run_lin_s(0, xctx, wn + DxD, fea_ctx, BB * LC, DD, DD, norm_b + DD, nullptr, 0);
    ln_warp<<<BB * LC / 8, 256>>>(fea_ctx, nullptr, fx, norm_g + DD, norm_be + DD);
    run_lin_s(0, fx, wkv0, nullptr, BB * LC, N2, DD, bkv0, nullptr, 0, kv0);

    cudaStreamWaitEvent(0, e1, 0);

    // ---- stage B (main)
    flash_attn<<<BB * HH, 256, FA_SMEM>>>(q0, kv0, kv0 + DD, ctx_mask, a0,
                                          LU, LC, LU, 1, LU, N2, 0.125f);
    run_lin_s(0, a0, wo, cur_attn, BB * LU, DD, DD, bo, fea_cur, 0);
    ln_warp<<<BB * LU / 8, 256>>>(cur_attn, nullptr, lnb, ln_g, ln_b);
    run_lin_s(0, lnb, w1, nullptr, BB * LU, DFF, DD, b1, nullptr, 1, ffh);
    run_lin_s(0, ffh, w2, cur_out, BB * LU, DD, DFF, b2, cur_attn, 0, co);

    // ---- stage C (main): fused K1|V1
    run_lin_s(0, co, wkv1, nullptr, BB * LU, N2, DD, bkv1, nullptr, 0, kv1);

    cudaStreamWaitEvent(0, e2, 0);

    flash_attn<<<BB * HH, 256, FA_SMEM>>>(q1, kv1, kv1 + DD, utt_mask, a1,
                                          SS, LU, 1, BB, SS, N2, 0.125f);

    run_lin_s(0, a1, wo + DxD, proj1, BB * SS, DD, DD, bo + DD, nullptr, 0);
    va_kernel<<<(SS * BB * DD + 255) / 256, 256>>>(fea_slots, proj1, va);

    ln_warp<<<SS * BB / 8, 256>>>(va, nullptr, lnb, ln_g + DD, ln_b + DD);
    run_lin_s(0, lnb, w1 + DD * DFF, nullptr, SS * BB, DFF, DD, b1 + DFF, nullptr, 1, ffh);
    run_lin_s(0, ffh, w2 + DFF * DD, slots_out, SS * BB, DD, DFF, b2 + DD, va, 0);
}